// round 8
// baseline (speedup 1.0000x reference)
#include <cuda_runtime.h>
#include <cuda_fp16.h>
#include <cstdint>

#define BB 8
#define SS 1024
#define DD 512
#define NHEADS 8
#define DHEAD 64
#define MROWS (BB*SS)   // 8192

// ---------------- scratch (no allocation allowed) ----------------
// fp16 split planes: [Qh|Ql|Kh|Kl|Vh], each [B*H][S][64]
#define PLANE ((size_t)4194304)
__device__ __half gP[5*PLANE];
__device__ __half gA[(size_t)MROWS*2048];       // [xs_h | xt_h | xs_l | xt_l]
__device__ __half gHs[(size_t)MROWS*1024];      // [H_h | H_l]
__device__ __half gBt[(size_t)3*512*2048];      // per-z W^T k-blocks [W1h,W2h,W1h,W2h]
__device__ __half gWoT[(size_t)512*1024];       // Wo^T k-blocks [Woh,Woh]

// ---------------- warp-mma helpers ----------------
__device__ __forceinline__ void ldsm4(uint32_t* r, uint32_t addr)
{
    asm volatile("ldmatrix.sync.aligned.m8n8.x4.shared.b16 {%0,%1,%2,%3}, [%4];"
        : "=r"(r[0]), "=r"(r[1]), "=r"(r[2]), "=r"(r[3]) : "r"(addr));
}

__device__ __forceinline__ void ldsm4t(uint32_t* r, uint32_t addr)
{
    asm volatile("ldmatrix.sync.aligned.m8n8.x4.trans.shared.b16 {%0,%1,%2,%3}, [%4];"
        : "=r"(r[0]), "=r"(r[1]), "=r"(r[2]), "=r"(r[3]) : "r"(addr));
}

__device__ __forceinline__ void mma16816(float* c, const uint32_t* a, const uint32_t* b)
{
    asm volatile(
        "mma.sync.aligned.m16n8k16.row.col.f32.f16.f16.f32 "
        "{%0,%1,%2,%3}, {%4,%5,%6,%7}, {%8,%9}, {%0,%1,%2,%3};"
        : "+f"(c[0]), "+f"(c[1]), "+f"(c[2]), "+f"(c[3])
        : "r"(a[0]), "r"(a[1]), "r"(a[2]), "r"(a[3]), "r"(b[0]), "r"(b[1]));
}

__device__ __forceinline__ void split2(float2 v, uint32_t& hi, uint32_t& lo)
{
    __half hx = __float2half_rn(v.x);
    __half hy = __float2half_rn(v.y);
    float rx = v.x - __half2float(hx);
    float ry = v.y - __half2float(hy);
    hi = ((uint32_t)__half_as_ushort(hy) << 16) | (uint32_t)__half_as_ushort(hx);
    lo = ((uint32_t)__half_as_ushort(__float2half_rn(ry)) << 16)
       | (uint32_t)__half_as_ushort(__float2half_rn(rx));
}

// ---------------------------------------------------------------------------
// fused prep kernel (A split, W pack, Wo pack) — one launch
// ---------------------------------------------------------------------------
#define PREPA_BLKS 16384
#define PREPW_BLKS 12288
#define PREPWO_BLKS 2048

__global__ void prep_all(const float* __restrict__ xs, const float* __restrict__ xt,
                         const float* __restrict__ Wqs, const float* __restrict__ Wks,
                         const float* __restrict__ Wvs, const float* __restrict__ Wqt,
                         const float* __restrict__ Wkt, const float* __restrict__ Wvt,
                         const float* __restrict__ Wo)
{
    int bid = blockIdx.x;
    int tid = threadIdx.x;
    if (bid < PREPA_BLKS) {
        int r = bid >> 1;
        int c = (bid & 1) * 256 + tid;
        float a = xs[(size_t)r*DD + c];
        float b = xt[(size_t)r*DD + c];
        __half ah = __float2half_rn(a);
        __half bh = __float2half_rn(b);
        __half* row = gA + (size_t)r*2048;
        row[c]        = ah;
        row[512 + c]  = bh;
        row[1024 + c] = __float2half_rn(a - __half2float(ah));
        row[1536 + c] = __float2half_rn(b - __half2float(bh));
    } else if (bid < PREPA_BLKS + PREPW_BLKS) {
        int idx = (bid - PREPA_BLKS) * 256 + tid;     // 3*512*2048
        int z   = idx / (512*2048);
        int rem = idx % (512*2048);
        int n   = rem / 2048;
        int k   = rem % 2048;
        const float* W1 = (z==0) ? Wqs : ((z==1) ? Wks : Wvs);
        const float* W2 = (z==0) ? Wqt : ((z==1) ? Wkt : Wvt);
        int kh = k >> 9, ks = k & 511;
        const float* M = (kh & 1) ? W2 : W1;
        gBt[idx] = __float2half_rn(M[(size_t)ks*DD + n]);
    } else {
        int idx = (bid - PREPA_BLKS - PREPW_BLKS) * 256 + tid;  // 512*1024
        int ks = idx & 511;
        gWoT[idx] = __float2half_rn(Wo[(size_t)ks*DD + ((idx >> 10) << 0 ? 0 : 0) + ( (idx / 1024) )]);
    }
}

// NOTE: the Wo branch above is replaced by a correct dedicated small kernel to
// avoid convoluted indexing mistakes:
__global__ void prep_Wo2(const float* __restrict__ Wo)
{
    int idx = blockIdx.x * 256 + threadIdx.x;      // 512*1024
    int n = idx / 1024;
    int k = idx % 1024;
    int ks = k & 511;
    gWoT[idx] = __float2half_rn(Wo[(size_t)ks*DD + n]);
}

// ---------------------------------------------------------------------------
// fp16 mma.sync GEMM: 128 threads, 4 warps (2x2), warp tile 64x64,
// block 128x128, BK=64, 3-stage cp.async, SW128 swizzle, 1 sync/chunk.
// mode 0: QKV -> fp16 hi/lo planes gP ; mode 1: OUT -> fp32 outp
// ---------------------------------------------------------------------------
__global__ __launch_bounds__(128)
void mma_gemm(int mode, float* __restrict__ outp, const float* __restrict__ WKb)
{
    extern __shared__ __half smg[];

    const __half* A;
    const __half* Bt;
    int aW, kEff, nChunks;
    const int z = blockIdx.z;
    if (mode == 0) {
        A = gA; aW = 2048; kEff = 2048; nChunks = 32;
        Bt = gBt + (size_t)z * 512 * 2048;
    } else {
        A = gHs; aW = 1024; kEff = 1024; nChunks = 16;
        Bt = gWoT;
    }

    const int mBase = blockIdx.y * 128;
    const int nBase = blockIdx.x * 128;
    const int t    = threadIdx.x;
    const int warp = t >> 5;
    const int lane = t & 31;
    const int wm   = warp >> 1;        // 0..1
    const int wn   = warp & 1;         // 0..1

    const uint32_t sBase = (uint32_t)__cvta_generic_to_shared(smg);

    const int ldRow = t >> 3;          // 0..15
    const int ldSeg = t & 7;
    const uint32_t ldSw = ((uint32_t)ldRow << 7)
                        + (((uint32_t)ldSeg << 4) ^ (((uint32_t)ldRow & 7) << 4));

    float acc[4][8][4];
#pragma unroll
    for (int i = 0; i < 4; i++)
#pragma unroll
        for (int j = 0; j < 8; j++)
#pragma unroll
            for (int q = 0; q < 4; q++) acc[i][j][q] = 0.f;

#define LOAD_CHUNK(cc, buf) do { \
    const __half* Ag_ = A + (size_t)(mBase + ldRow) * aW + ((cc) << 6) + ldSeg * 8; \
    const __half* Bg_ = Bt + (size_t)(nBase + ldRow) * kEff + (size_t)(cc) * 64 + ldSeg * 8; \
    uint32_t da_ = sBase + (buf)*32768u + ldSw; \
    uint32_t db_ = da_ + 16384u; \
    _Pragma("unroll") \
    for (int rr_ = 0; rr_ < 8; rr_++) { \
        asm volatile("cp.async.cg.shared.global [%0], [%1], 16;" \
            :: "r"(da_ + rr_*2048u), "l"(__cvta_generic_to_global((const void*)(Ag_ + (size_t)rr_*16*aW)))); \
        asm volatile("cp.async.cg.shared.global [%0], [%1], 16;" \
            :: "r"(db_ + rr_*2048u), "l"(__cvta_generic_to_global((const void*)(Bg_ + (size_t)rr_*16*kEff)))); \
    } \
    asm volatile("cp.async.commit_group;" ::: "memory"); \
} while (0)

    LOAD_CHUNK(0, 0);
    LOAD_CHUNK(1, 1);

    const int aRowL = wm*64 + (lane & 15);
    const int aColB = (((lane >> 4) << 3)) * 2;
    const uint32_t aSw = ((uint32_t)(lane & 7)) << 4;
    const int bRowL = wn*64 + ((lane >> 4) << 3) + (lane & 7);
    const int bColB = ((((lane >> 3) & 1) << 3)) * 2;
    const uint32_t bSw = ((uint32_t)(lane & 7)) << 4;

    for (int c = 0; c < nChunks; c++) {
        const int buf = c % 3;
        if (c + 1 < nChunks) { asm volatile("cp.async.wait_group 1;" ::: "memory"); }
        else                 { asm volatile("cp.async.wait_group 0;" ::: "memory"); }
        __syncthreads();
        if (c + 2 < nChunks) LOAD_CHUNK(c + 2, (c + 2) % 3);

        const uint32_t aB = sBase + buf*32768u;
        const uint32_t bB = aB + 16384u;
#pragma unroll
        for (int ks = 0; ks < 4; ks++) {
            const uint32_t kb = (uint32_t)(ks << 5);
            uint32_t afr[4][4];
#pragma unroll
            for (int mf = 0; mf < 4; mf++)
                ldsm4(afr[mf], aB + (uint32_t)((aRowL + mf*16) << 7) + ((kb + aColB) ^ aSw));
            uint32_t bfr[8][2];
#pragma unroll
            for (int nf2 = 0; nf2 < 4; nf2++) {
                uint32_t r4[4];
                ldsm4(r4, bB + (uint32_t)((bRowL + nf2*16) << 7) + ((kb + bColB) ^ bSw));
                bfr[nf2*2+0][0] = r4[0]; bfr[nf2*2+0][1] = r4[1];
                bfr[nf2*2+1][0] = r4[2]; bfr[nf2*2+1][1] = r4[3];
            }
#pragma unroll
            for (int mf = 0; mf < 4; mf++)
#pragma unroll
                for (int nf = 0; nf < 8; nf++)
                    mma16816(acc[mf][nf], afr[mf], bfr[nf]);
        }
    }

    const int g   = lane >> 2;
    const int tig = lane & 3;

    if (mode == 0) {
        __half* Ph = gP + (size_t)((z==0) ? 0 : (z==1) ? 2 : 4) * PLANE;
        __half* Pl = Ph + PLANE;
        const int hh = (nBase + wn*64) >> 6;
#pragma unroll
        for (int mf = 0; mf < 4; mf++) {
            int row0 = mBase + wm*64 + mf*16 + g;
            int bb = row0 >> 10, s0 = row0 & (SS-1);
#pragma unroll
            for (int nf = 0; nf < 8; nf++) {
                int d = nf*8 + tig*2;
                float c0 = acc[mf][nf][0], c1 = acc[mf][nf][1];
                float c2 = acc[mf][nf][2], c3 = acc[mf][nf][3];
                if (z == 0) { c0 *= 0.125f; c1 *= 0.125f; c2 *= 0.125f; c3 *= 0.125f; }
                else if (z == 1) {
                    c0 += WKb[d*SS + s0];       c1 += WKb[(d+1)*SS + s0];
                    c2 += WKb[d*SS + s0 + 8];   c3 += WKb[(d+1)*SS + s0 + 8];
                }
                size_t off0 = ((size_t)(bb*NHEADS + hh)*SS + s0)*64 + d;
                uint32_t hi, lo;
                split2(make_float2(c0, c1), hi, lo);
                *(uint32_t*)&Ph[off0] = hi;
                if (z < 2) *(uint32_t*)&Pl[off0] = lo;
                split2(make_float2(c2, c3), hi, lo);
                *(uint32_t*)&Ph[off0 + 512] = hi;
                if (z < 2) *(uint32_t*)&Pl[off0 + 512] = lo;
            }
        }
    } else {
#pragma unroll
        for (int mf = 0; mf < 4; mf++) {
            int row0 = mBase + wm*64 + mf*16 + g;
#pragma unroll
            for (int nf = 0; nf < 8; nf++) {
                int col = nBase + wn*64 + nf*8 + tig*2;
                *(float2*)&outp[(size_t)row0*DD + col]
                    = make_float2(acc[mf][nf][0], acc[mf][nf][1]);
                *(float2*)&outp[(size_t)(row0+8)*DD + col]
                    = make_float2(acc[mf][nf][2], acc[mf][nf][3]);
            }
        }
    }
#undef LOAD_CHUNK
}

// ---------------------------------------------------------------------------
// fp16 causal flash attention: q-tile 256 (8 warps x 32 rows), k-tile 64,
// scores 3-term, PV 2-term, double-buffered smem, 1 sync/tile.
// ---------------------------------------------------------------------------
__global__ __launch_bounds__(256, 1) void attn_mma()
{
    extern __shared__ __half sma[];

    const int bx = blockIdx.x;
    const int qt = 3 - (bx >> 6);            // big q-tiles first
    const int bh = bx & 63;
    const int b = bh >> 3, h = bh & 7;
    const int t = threadIdx.x, warp = t >> 5, lane = t & 31;
    const int g = lane >> 2, tig = lane & 3;

    const size_t bhOff = (size_t)(b*NHEADS + h) * SS * 64;
    const __half* pQh = gP + bhOff;
    const __half* pQl = gP + PLANE   + bhOff;
    const __half* pKh = gP + 2*PLANE + bhOff;
    const __half* pKl = gP + 3*PLANE + bhOff;
    const __half* pVh = gP + 4*PLANE + bhOff;

    const int roff  = qt*256 + warp*32;      // this warp's first q row
    const int dtile = roff >> 6;             // diagonal k-tile index

    uint32_t qh[2][4][4], ql[2][4][4];
#pragma unroll
    for (int fg = 0; fg < 2; fg++) {
        const size_t q0 = (size_t)(roff + fg*16 + g) * 64 + 2*tig;
        const size_t q1 = q0 + 8*64;
#pragma unroll
        for (int s = 0; s < 4; s++) {
            qh[fg][s][0] = *(const uint32_t*)&pQh[q0 + s*16];
            qh[fg][s][1] = *(const uint32_t*)&pQh[q1 + s*16];
            qh[fg][s][2] = *(const uint32_t*)&pQh[q0 + s*16 + 8];
            qh[fg][s][3] = *(const uint32_t*)&pQh[q1 + s*16 + 8];
            ql[fg][s][0] = *(const uint32_t*)&pQl[q0 + s*16];
            ql[fg][s][1] = *(const uint32_t*)&pQl[q1 + s*16];
            ql[fg][s][2] = *(const uint32_t*)&pQl[q0 + s*16 + 8];
            ql[fg][s][3] = *(const uint32_t*)&pQl[q1 + s*16 + 8];
        }
    }

    float o[2][8][4];
#pragma unroll
    for (int fg = 0; fg < 2; fg++)
#pragma unroll
        for (int nf = 0; nf < 8; nf++)
#pragma unroll
            for (int j = 0; j < 4; j++) o[fg][nf][j] = 0.f;
    float m[2][2], l[2][2];
#pragma unroll
    for (int fg = 0; fg < 2; fg++) { m[fg][0] = m[fg][1] = -1e30f; l[fg][0] = l[fg][1] = 0.f; }

    const uint32_t smB = (uint32_t)__cvta_generic_to_shared(sma);
    const int lr8 = t >> 2;
    const int ls  = t & 3;
    const uint32_t swst = ((uint32_t)lr8 & 7) << 4;

#define LOAD_TILE(kt_, buf_) do { \
    const size_t ro_ = (size_t)((kt_)*64 + lr8) * 64; \
    uint32_t db_ = smB + (uint32_t)((buf_)*24576) + (uint32_t)(lr8*128); \
    _Pragma("unroll") \
    for (int sg_ = 0; sg_ < 2; sg_++) { \
        int seg_ = ls*2 + sg_; \
        uint32_t co_ = ((uint32_t)(seg_*16)) ^ swst; \
        asm volatile("cp.async.cg.shared.global [%0], [%1], 16;" \
            :: "r"(db_ + co_),          "l"(__cvta_generic_to_global((const void*)(pKh + ro_ + seg_*8)))); \
        asm volatile("cp.async.cg.shared.global [%0], [%1], 16;" \
            :: "r"(db_ + 8192u + co_),  "l"(__cvta_generic_to_global((const void*)(pKl + ro_ + seg_*8)))); \
        asm volatile("cp.async.cg.shared.global [%0], [%1], 16;" \
            :: "r"(db_ + 16384u + co_), "l"(__cvta_generic_to_global((const void*)(pVh + ro_ + seg_*8)))); \
    } \
    asm volatile("cp.async.commit_group;" ::: "memory"); \
} while (0)

    const uint32_t swf = (uint32_t)(lane & 7) << 4;
    const uint32_t kRowB = (uint32_t)((((lane>>4)<<3) | (lane&7)) * 128);
    const uint32_t kColS = (uint32_t)(((lane>>3)&1) << 4);
    const uint32_t vRowB = (uint32_t)((lane & 15) * 128);
    const uint32_t vColS = (uint32_t)((lane>>4) << 4);

    const int nkt = 4*qt + 4;
    LOAD_TILE(0, 0);

    for (int kt = 0; kt < nkt; kt++) {
        asm volatile("cp.async.wait_group 0;" ::: "memory");
        __syncthreads();
        if (kt + 1 < nkt) LOAD_TILE(kt + 1, (kt + 1) & 1);

        const uint32_t bufB = smB + (uint32_t)((kt & 1) * 24576);
        if (kt <= dtile) {
            float s[2][8][4];
#pragma unroll
            for (int fg = 0; fg < 2; fg++)
#pragma unroll
                for (int nf = 0; nf < 8; nf++)
#pragma unroll
                    for (int j = 0; j < 4; j++) s[fg][nf][j] = 0.f;

#pragma unroll
            for (int nfp = 0; nfp < 4; nfp++) {
                const uint32_t rowOff = bufB + kRowB + (uint32_t)(nfp*2048);
#pragma unroll
                for (int ks = 0; ks < 4; ks++) {
                    uint32_t kr[4];
                    ldsm4(kr, rowOff + (((uint32_t)(ks*32) + kColS) ^ swf));
#pragma unroll
                    for (int fg = 0; fg < 2; fg++) {
                        mma16816(s[fg][2*nfp],   qh[fg][ks], kr);
                        mma16816(s[fg][2*nfp+1], qh[fg][ks], kr + 2);
                        mma16816(s[fg][2*nfp],   ql[fg][ks], kr);
                        mma16816(s[fg][2*nfp+1], ql[fg][ks], kr + 2);
                    }
                    ldsm4(kr, rowOff + 8192u + (((uint32_t)(ks*32) + kColS) ^ swf));
#pragma unroll
                    for (int fg = 0; fg < 2; fg++) {
                        mma16816(s[fg][2*nfp],   qh[fg][ks], kr);
                        mma16816(s[fg][2*nfp+1], qh[fg][ks], kr + 2);
                    }
                }
            }

            if (kt == dtile) {
                const int key0 = kt*64;
#pragma unroll
                for (int fg = 0; fg < 2; fg++) {
                    int r0 = roff + fg*16 + g, r1 = r0 + 8;
#pragma unroll
                    for (int nf = 0; nf < 8; nf++) {
                        int kc = key0 + nf*8 + 2*tig;
                        if (kc     > r0) s[fg][nf][0] = -1e30f;
                        if (kc + 1 > r0) s[fg][nf][1] = -1e30f;
                        if (kc     > r1) s[fg][nf][2] = -1e30f;
                        if (kc + 1 > r1) s[fg][nf][3] = -1e30f;
                    }
                }
            }

#pragma unroll
            for (int fg = 0; fg < 2; fg++) {
                float mx0 = -1e30f, mx1 = -1e30f;
#pragma unroll
                for (int nf = 0; nf < 8; nf++) {
                    mx0 = fmaxf(mx0, fmaxf(s[fg][nf][0], s[fg][nf][1]));
                    mx1 = fmaxf(mx1, fmaxf(s[fg][nf][2], s[fg][nf][3]));
                }
                mx0 = fmaxf(mx0, __shfl_xor_sync(0xffffffffu, mx0, 1));
                mx0 = fmaxf(mx0, __shfl_xor_sync(0xffffffffu, mx0, 2));
                mx1 = fmaxf(mx1, __shfl_xor_sync(0xffffffffu, mx1, 1));
                mx1 = fmaxf(mx1, __shfl_xor_sync(0xffffffffu, mx1, 2));
                float mn0 = fmaxf(m[fg][0], mx0), mn1 = fmaxf(m[fg][1], mx1);
                float a0 = __expf(m[fg][0] - mn0), a1 = __expf(m[fg][1] - mn1);
                m[fg][0] = mn0; m[fg][1] = mn1;
                float sum0 = 0.f, sum1 = 0.f;
#pragma unroll
                for (int nf = 0; nf < 8; nf++) {
                    s[fg][nf][0] = __expf(s[fg][nf][0] - mn0);
                    s[fg][nf][1] = __expf(s[fg][nf][1] - mn0);
                    s[fg][nf][2] = __expf(s[fg][nf][2] - mn1);
                    s[fg][nf][3] = __expf(s[fg][nf][3] - mn1);
                    sum0 += s[fg][nf][0] + s[fg][nf][1];
                    sum1 += s[fg][nf][2] + s[fg][nf][3];
                }
                sum0 += __shfl_xor_sync(0xffffffffu, sum0, 1);
                sum0 += __shfl_xor_sync(0xffffffffu, sum0, 2);
                sum1 += __shfl_xor_sync(0xffffffffu, sum1, 1);
                sum1 += __shfl_xor_sync(0xffffffffu, sum1, 2);
                l[fg][0] = l[fg][0]*a0 + sum0;
                l[fg][1] = l[fg][1]*a1 + sum1;
#pragma unroll
                for (int nf = 0; nf < 8; nf++) {
                    o[fg][nf][0] *= a0; o[fg][nf][1] *= a0;
                    o[fg][nf][2] *= a1; o[fg][nf][3] *= a1;
                }
            }

            // O += (Ph + Pl) @ Vh
#pragma unroll
            for (int sk = 0; sk < 4; sk++) {
                uint32_t ph[2][4], pl[2][4];
#pragma unroll
                for (int fg = 0; fg < 2; fg++) {
                    split2(make_float2(s[fg][2*sk][0],   s[fg][2*sk][1]),   ph[fg][0], pl[fg][0]);
                    split2(make_float2(s[fg][2*sk][2],   s[fg][2*sk][3]),   ph[fg][1], pl[fg][1]);
                    split2(make_float2(s[fg][2*sk+1][0], s[fg][2*sk+1][1]), ph[fg][2], pl[fg][2]);
                    split2(make_float2(s[fg][2*sk+1][2], s[fg][2*sk+1][3]), ph[fg][3], pl[fg][3]);
                }
                const uint32_t vOff = bufB + 16384u + vRowB + (uint32_t)(sk*2048);
#pragma unroll
                for (int nb = 0; nb < 4; nb++) {
                    uint32_t vh4[4];
                    uint32_t co = (((uint32_t)(nb*32) + vColS) ^ swf);
                    ldsm4t(vh4, vOff + co);
#pragma unroll
                    for (int fg = 0; fg < 2; fg++) {
                        mma16816(o[fg][2*nb],   ph[fg], vh4);
                        mma16816(o[fg][2*nb+1], ph[fg], vh4 + 2);
                        mma16816(o[fg][2*nb],   pl[fg], vh4);
                        mma16816(o[fg][2*nb+1], pl[fg], vh4 + 2);
                    }
                }
            }
        }
    }

#pragma unroll
    for (int fg = 0; fg < 2; fg++) {
        int rloc0 = roff + fg*16 + g;
        float i0 = 1.f / l[fg][0], i1 = 1.f / l[fg][1];
        __half* base0 = gHs + (size_t)(b*SS + rloc0) * 1024;
        __half* base1 = base0 + (size_t)8 * 1024;
#pragma unroll
        for (int nf = 0; nf < 8; nf++) {
            int col = h*64 + nf*8 + 2*tig;
            uint32_t hi, lo;
            split2(make_float2(o[fg][nf][0]*i0, o[fg][nf][1]*i0), hi, lo);
            *(uint32_t*)&base0[col]       = hi;
            *(uint32_t*)&base0[512 + col] = lo;
            split2(make_float2(o[fg][nf][2]*i1, o[fg][nf][3]*i1), hi, lo);
            *(uint32_t*)&base1[col]       = hi;
            *(uint32_t*)&base1[512 + col] = lo;
        }
    }
#undef LOAD_TILE
}

// ---------------------------------------------------------------------------
extern "C" void kernel_launch(void* const* d_in, const int* in_sizes, int n_in,
                              void* d_out, int out_size)
{
    const float* xs  = (const float*)d_in[0];
    const float* xt  = (const float*)d_in[1];
    const float* Wqs = (const float*)d_in[2];
    const float* Wks = (const float*)d_in[3];
    const float* Wvs = (const float*)d_in[4];
    const float* Wqt = (const float*)d_in[5];
    const float* Wkt = (const float*)d_in[6];
    const float* Wvt = (const float*)d_in[7];
    const float* WKb = (const float*)d_in[8];
    const float* Wo  = (const float*)d_in[9];
    float* out = (float*)d_out;

    const int GEMM_SMEM = 3 * 32768;      // 98304
    const int ATTN_SMEM = 2 * 24576;      // 49152
    cudaFuncSetAttribute(mma_gemm, cudaFuncAttributeMaxDynamicSharedMemorySize, GEMM_SMEM);
    cudaFuncSetAttribute(attn_mma, cudaFuncAttributeMaxDynamicSharedMemorySize, ATTN_SMEM);

    prep_all<<<PREPA_BLKS + PREPW_BLKS, 256>>>(xs, xt, Wqs, Wks, Wvs, Wqt, Wkt, Wvt, Wo);
    prep_Wo2<<<PREPWO_BLKS, 256>>>(Wo);

    mma_gemm<<<dim3(4, 64, 3), 128, GEMM_SMEM>>>(0, nullptr, WKb);
    attn_mma<<<256, 256, ATTN_SMEM>>>();
    mma_gemm<<<dim3(4, 64, 1), 128, GEMM_SMEM>>>(1, out, WKb);
}

// round 9
// speedup vs baseline: 1.2227x; 1.2227x over previous
#include <cuda_runtime.h>
#include <cuda_fp16.h>
#include <cstdint>

#define BB 8
#define SS 1024
#define DD 512
#define NHEADS 8
#define DHEAD 64
#define MROWS (BB*SS)   // 8192

// ---------------- scratch (no allocation allowed) ----------------
// fp16 split planes: [Qh|Ql|Kh|Kl|Vh], each [B*H][S][64]
#define PLANE ((size_t)4194304)
__device__ __half gP[5*PLANE];
__device__ __half gA[(size_t)MROWS*2048];       // [xs_h | xt_h | xs_l | xt_l]
__device__ __half gHs[(size_t)MROWS*1024];      // [H_h | H_l]
__device__ __half gBt[(size_t)3*512*2048];      // per-z W^T k-blocks [W1h,W2h,W1h,W2h]
__device__ __half gWoT[(size_t)512*1024];       // Wo^T k-blocks [Woh,Woh]

// ---------------- warp-mma helpers ----------------
__device__ __forceinline__ void ldsm4(uint32_t* r, uint32_t addr)
{
    asm volatile("ldmatrix.sync.aligned.m8n8.x4.shared.b16 {%0,%1,%2,%3}, [%4];"
        : "=r"(r[0]), "=r"(r[1]), "=r"(r[2]), "=r"(r[3]) : "r"(addr));
}

__device__ __forceinline__ void ldsm4t(uint32_t* r, uint32_t addr)
{
    asm volatile("ldmatrix.sync.aligned.m8n8.x4.trans.shared.b16 {%0,%1,%2,%3}, [%4];"
        : "=r"(r[0]), "=r"(r[1]), "=r"(r[2]), "=r"(r[3]) : "r"(addr));
}

__device__ __forceinline__ void mma16816(float* c, const uint32_t* a, const uint32_t* b)
{
    asm volatile(
        "mma.sync.aligned.m16n8k16.row.col.f32.f16.f16.f32 "
        "{%0,%1,%2,%3}, {%4,%5,%6,%7}, {%8,%9}, {%0,%1,%2,%3};"
        : "+f"(c[0]), "+f"(c[1]), "+f"(c[2]), "+f"(c[3])
        : "r"(a[0]), "r"(a[1]), "r"(a[2]), "r"(a[3]), "r"(b[0]), "r"(b[1]));
}

__device__ __forceinline__ void split2(float2 v, uint32_t& hi, uint32_t& lo)
{
    __half hx = __float2half_rn(v.x);
    __half hy = __float2half_rn(v.y);
    float rx = v.x - __half2float(hx);
    float ry = v.y - __half2float(hy);
    hi = ((uint32_t)__half_as_ushort(hy) << 16) | (uint32_t)__half_as_ushort(hx);
    lo = ((uint32_t)__half_as_ushort(__float2half_rn(ry)) << 16)
       | (uint32_t)__half_as_ushort(__float2half_rn(rx));
}

// ---------------------------------------------------------------------------
// fused prep kernel (A split + W pack), plus small Wo pack
// ---------------------------------------------------------------------------
#define PREPA_BLKS 16384
#define PREPW_BLKS 12288
#define PREPWO_BLKS 2048

__global__ void prep_all(const float* __restrict__ xs, const float* __restrict__ xt,
                         const float* __restrict__ Wqs, const float* __restrict__ Wks,
                         const float* __restrict__ Wvs, const float* __restrict__ Wqt,
                         const float* __restrict__ Wkt, const float* __restrict__ Wvt)
{
    int bid = blockIdx.x;
    int tid = threadIdx.x;
    if (bid < PREPA_BLKS) {
        int r = bid >> 1;
        int c = (bid & 1) * 256 + tid;
        float a = xs[(size_t)r*DD + c];
        float b = xt[(size_t)r*DD + c];
        __half ah = __float2half_rn(a);
        __half bh = __float2half_rn(b);
        __half* row = gA + (size_t)r*2048;
        row[c]        = ah;
        row[512 + c]  = bh;
        row[1024 + c] = __float2half_rn(a - __half2float(ah));
        row[1536 + c] = __float2half_rn(b - __half2float(bh));
    } else {
        int idx = (bid - PREPA_BLKS) * 256 + tid;     // 3*512*2048
        int z   = idx / (512*2048);
        int rem = idx % (512*2048);
        int n   = rem / 2048;
        int k   = rem % 2048;
        const float* W1 = (z==0) ? Wqs : ((z==1) ? Wks : Wvs);
        const float* W2 = (z==0) ? Wqt : ((z==1) ? Wkt : Wvt);
        int kh = k >> 9, ks = k & 511;
        const float* M = (kh & 1) ? W2 : W1;
        gBt[idx] = __float2half_rn(M[(size_t)ks*DD + n]);
    }
}

__global__ void prep_Wo2(const float* __restrict__ Wo)
{
    int idx = blockIdx.x * 256 + threadIdx.x;      // 512*1024
    int n = idx / 1024;
    int k = idx % 1024;
    int ks = k & 511;
    gWoT[idx] = __float2half_rn(Wo[(size_t)ks*DD + n]);
}

// ---------------------------------------------------------------------------
// fp16 mma.sync GEMM (round-7 proven config): 256 threads, 8 warps (2x4),
// warp tile 64x32, block 128x128, BK=64, 3-stage cp.async, SW128 swizzle.
// mode 0: QKV -> fp16 hi/lo planes gP (V: hi-only, lo K-chunks skipped)
// mode 1: OUT -> fp32 outp
// ---------------------------------------------------------------------------
__global__ __launch_bounds__(256)
void mma_gemm(int mode, float* __restrict__ outp, const float* __restrict__ WKb)
{
    extern __shared__ __half smg[];

    const __half* A;
    const __half* Bt;
    int aW, kEff, nChunks;
    const int z = blockIdx.z;
    if (mode == 0) {
        A = gA; aW = 2048; kEff = 2048;
        nChunks = (z == 2) ? 16 : 32;     // V: skip lo residual chunks (sub-fp16-ulp)
        Bt = gBt + (size_t)z * 512 * 2048;
    } else {
        A = gHs; aW = 1024; kEff = 1024; nChunks = 16;
        Bt = gWoT;
    }

    const int mBase = blockIdx.y * 128;
    const int nBase = blockIdx.x * 128;
    const int t    = threadIdx.x;
    const int warp = t >> 5;
    const int lane = t & 31;
    const int wm   = warp >> 2;
    const int wn   = warp & 3;

    const uint32_t sBase = (uint32_t)__cvta_generic_to_shared(smg);

    const int ldRow = t >> 3;
    const int ldSeg = t & 7;
    const uint32_t ldSw = ((uint32_t)ldRow << 7)
                        + (((uint32_t)ldSeg << 4) ^ (((uint32_t)ldRow & 7) << 4));

    float acc[4][4][4];
#pragma unroll
    for (int i = 0; i < 4; i++)
#pragma unroll
        for (int j = 0; j < 4; j++)
#pragma unroll
            for (int q = 0; q < 4; q++) acc[i][j][q] = 0.f;

#define LOAD_CHUNK(cc, buf) do { \
    const __half* Ag_ = A + (size_t)(mBase + ldRow) * aW + ((cc) << 6) + ldSeg * 8; \
    const __half* Bg_ = Bt + (size_t)(nBase + ldRow) * kEff + (size_t)(cc) * 64 + ldSeg * 8; \
    uint32_t da_ = sBase + (buf)*32768u + ldSw; \
    uint32_t db_ = da_ + 16384u; \
    _Pragma("unroll") \
    for (int rr_ = 0; rr_ < 4; rr_++) { \
        asm volatile("cp.async.cg.shared.global [%0], [%1], 16;" \
            :: "r"(da_ + rr_*4096u), "l"(__cvta_generic_to_global((const void*)(Ag_ + (size_t)rr_*32*aW)))); \
        asm volatile("cp.async.cg.shared.global [%0], [%1], 16;" \
            :: "r"(db_ + rr_*4096u), "l"(__cvta_generic_to_global((const void*)(Bg_ + (size_t)rr_*32*kEff)))); \
    } \
    asm volatile("cp.async.commit_group;" ::: "memory"); \
} while (0)

    LOAD_CHUNK(0, 0);
    LOAD_CHUNK(1, 1);

    const int aRowL = wm*64 + (lane & 15);
    const int aColB = (((lane >> 4) << 3)) * 2;
    const uint32_t aSw = ((uint32_t)aRowL & 7) << 4;
    const int bRowL = wn*32 + ((lane >> 4) << 3) + (lane & 7);
    const int bColB = ((((lane >> 3) & 1) << 3)) * 2;
    const uint32_t bSw = ((uint32_t)bRowL & 7) << 4;

    for (int c = 0; c < nChunks; c++) {
        const int buf = c % 3;
        if (c + 1 < nChunks) { asm volatile("cp.async.wait_group 1;" ::: "memory"); }
        else                 { asm volatile("cp.async.wait_group 0;" ::: "memory"); }
        __syncthreads();
        if (c + 2 < nChunks) LOAD_CHUNK(c + 2, (c + 2) % 3);

        const uint32_t aB = sBase + buf*32768u;
        const uint32_t bB = aB + 16384u;
#pragma unroll
        for (int ks = 0; ks < 4; ks++) {
            const uint32_t kb = (uint32_t)(ks << 5);
            uint32_t afr[4][4];
#pragma unroll
            for (int mf = 0; mf < 4; mf++)
                ldsm4(afr[mf], aB + (uint32_t)((aRowL + mf*16) << 7) + ((kb + aColB) ^ aSw));
            uint32_t bfr[4][2];
#pragma unroll
            for (int nfp = 0; nfp < 2; nfp++) {
                uint32_t r4[4];
                ldsm4(r4, bB + (uint32_t)((bRowL + nfp*16) << 7) + ((kb + bColB) ^ bSw));
                bfr[nfp*2+0][0] = r4[0]; bfr[nfp*2+0][1] = r4[1];
                bfr[nfp*2+1][0] = r4[2]; bfr[nfp*2+1][1] = r4[3];
            }
#pragma unroll
            for (int mf = 0; mf < 4; mf++)
#pragma unroll
                for (int nf = 0; nf < 4; nf++)
                    mma16816(acc[mf][nf], afr[mf], bfr[nf]);
        }
    }

    const int g   = lane >> 2;
    const int tig = lane & 3;

    if (mode == 0) {
        __half* Ph = gP + (size_t)((z==0) ? 0 : (z==1) ? 2 : 4) * PLANE;
        __half* Pl = Ph + PLANE;
#pragma unroll
        for (int mf = 0; mf < 4; mf++) {
            int row0 = mBase + wm*64 + mf*16 + g;
            int bb = row0 >> 10, s0 = row0 & (SS-1);
#pragma unroll
            for (int nf = 0; nf < 4; nf++) {
                int col = nBase + wn*32 + nf*8 + tig*2;
                int hh = col >> 6, d = col & 63;
                float c0 = acc[mf][nf][0], c1 = acc[mf][nf][1];
                float c2 = acc[mf][nf][2], c3 = acc[mf][nf][3];
                if (z == 0) { c0 *= 0.125f; c1 *= 0.125f; c2 *= 0.125f; c3 *= 0.125f; }
                else if (z == 1) {
                    c0 += WKb[d*SS + s0];       c1 += WKb[(d+1)*SS + s0];
                    c2 += WKb[d*SS + s0 + 8];   c3 += WKb[(d+1)*SS + s0 + 8];
                }
                size_t off0 = ((size_t)(bb*NHEADS + hh)*SS + s0)*64 + d;
                uint32_t hi, lo;
                split2(make_float2(c0, c1), hi, lo);
                *(uint32_t*)&Ph[off0] = hi;
                if (z < 2) *(uint32_t*)&Pl[off0] = lo;
                split2(make_float2(c2, c3), hi, lo);
                *(uint32_t*)&Ph[off0 + 512] = hi;
                if (z < 2) *(uint32_t*)&Pl[off0 + 512] = lo;
            }
        }
    } else {
#pragma unroll
        for (int mf = 0; mf < 4; mf++) {
            int row0 = mBase + wm*64 + mf*16 + g;
#pragma unroll
            for (int nf = 0; nf < 4; nf++) {
                int col = nBase + wn*32 + nf*8 + tig*2;
                *(float2*)&outp[(size_t)row0*DD + col]
                    = make_float2(acc[mf][nf][0], acc[mf][nf][1]);
                *(float2*)&outp[(size_t)(row0+8)*DD + col]
                    = make_float2(acc[mf][nf][2], acc[mf][nf][3]);
            }
        }
    }
#undef LOAD_CHUNK
}

// ---------------------------------------------------------------------------
// fp16 causal flash attention (round-7 proven config): q-tile 128
// (8 warps x 16 rows), k-tile 64, scores 3-term, PV 2-term (Vh only),
// double-buffered smem, 1 sync/tile.
// ---------------------------------------------------------------------------
__global__ __launch_bounds__(256, 1) void attn_mma()
{
    extern __shared__ __half sma[];

    const int bx = blockIdx.x;
    const int qt = 7 - (bx >> 6);
    const int bh = bx & 63;
    const int b = bh >> 3, h = bh & 7;
    const int t = threadIdx.x, warp = t >> 5, lane = t & 31;
    const int g = lane >> 2, tig = lane & 3;

    const size_t bhOff = (size_t)(b*NHEADS + h) * SS * 64;
    const __half* pQh = gP + bhOff;
    const __half* pQl = gP + PLANE   + bhOff;
    const __half* pKh = gP + 2*PLANE + bhOff;
    const __half* pKl = gP + 3*PLANE + bhOff;
    const __half* pVh = gP + 4*PLANE + bhOff;

    const int rloc0 = qt*128 + warp*16 + g;
    const int rloc1 = rloc0 + 8;

    uint32_t qh[4][4], ql[4][4];
    {
        const size_t q0 = (size_t)rloc0 * 64 + 2*tig;
        const size_t q1 = (size_t)rloc1 * 64 + 2*tig;
#pragma unroll
        for (int s = 0; s < 4; s++) {
            qh[s][0] = *(const uint32_t*)&pQh[q0 + s*16];
            qh[s][1] = *(const uint32_t*)&pQh[q1 + s*16];
            qh[s][2] = *(const uint32_t*)&pQh[q0 + s*16 + 8];
            qh[s][3] = *(const uint32_t*)&pQh[q1 + s*16 + 8];
            ql[s][0] = *(const uint32_t*)&pQl[q0 + s*16];
            ql[s][1] = *(const uint32_t*)&pQl[q1 + s*16];
            ql[s][2] = *(const uint32_t*)&pQl[q0 + s*16 + 8];
            ql[s][3] = *(const uint32_t*)&pQl[q1 + s*16 + 8];
        }
    }

    float o[8][4];
#pragma unroll
    for (int nf = 0; nf < 8; nf++)
#pragma unroll
        for (int j = 0; j < 4; j++) o[nf][j] = 0.f;
    float m0 = -1e30f, m1 = -1e30f, l0 = 0.f, l1 = 0.f;

    const uint32_t smB = (uint32_t)__cvta_generic_to_shared(sma);
    const int lr8 = t >> 2;
    const int ls  = t & 3;
    const uint32_t swst = ((uint32_t)lr8 & 7) << 4;

#define LOAD_TILE(kt_, buf_) do { \
    const size_t ro_ = (size_t)((kt_)*64 + lr8) * 64; \
    uint32_t db_ = smB + (uint32_t)((buf_)*24576) + (uint32_t)(lr8*128); \
    _Pragma("unroll") \
    for (int sg_ = 0; sg_ < 2; sg_++) { \
        int seg_ = ls*2 + sg_; \
        uint32_t co_ = ((uint32_t)(seg_*16)) ^ swst; \
        asm volatile("cp.async.cg.shared.global [%0], [%1], 16;" \
            :: "r"(db_ + co_),          "l"(__cvta_generic_to_global((const void*)(pKh + ro_ + seg_*8)))); \
        asm volatile("cp.async.cg.shared.global [%0], [%1], 16;" \
            :: "r"(db_ + 8192u + co_),  "l"(__cvta_generic_to_global((const void*)(pKl + ro_ + seg_*8)))); \
        asm volatile("cp.async.cg.shared.global [%0], [%1], 16;" \
            :: "r"(db_ + 16384u + co_), "l"(__cvta_generic_to_global((const void*)(pVh + ro_ + seg_*8)))); \
    } \
    asm volatile("cp.async.commit_group;" ::: "memory"); \
} while (0)

    const uint32_t swf = (uint32_t)(lane & 7) << 4;
    const uint32_t kRowB = (uint32_t)((((lane>>4)<<3) | (lane&7)) * 128);
    const uint32_t kColS = (uint32_t)(((lane>>3)&1) << 4);
    const uint32_t vRowB = (uint32_t)((lane & 15) * 128);
    const uint32_t vColS = (uint32_t)((lane>>4) << 4);

    const int nkt = 2*qt + 2;
    LOAD_TILE(0, 0);

    for (int kt = 0; kt < nkt; kt++) {
        asm volatile("cp.async.wait_group 0;" ::: "memory");
        __syncthreads();
        if (kt + 1 < nkt) LOAD_TILE(kt + 1, (kt + 1) & 1);

        const uint32_t bufB = smB + (uint32_t)((kt & 1) * 24576);
        const bool active = (qt*128 + warp*16 + 15) >= kt*64;
        if (active) {
            float s[8][4];
#pragma unroll
            for (int nf = 0; nf < 8; nf++)
#pragma unroll
                for (int j = 0; j < 4; j++) s[nf][j] = 0.f;

#pragma unroll
            for (int nfp = 0; nfp < 4; nfp++) {
                const uint32_t rowOff = bufB + kRowB + (uint32_t)(nfp*2048);
#pragma unroll
                for (int ks = 0; ks < 4; ks++) {
                    uint32_t kr[4];
                    ldsm4(kr, rowOff + (((uint32_t)(ks*32) + kColS) ^ swf));
                    mma16816(s[2*nfp],   qh[ks], kr);
                    mma16816(s[2*nfp+1], qh[ks], kr + 2);
                    mma16816(s[2*nfp],   ql[ks], kr);
                    mma16816(s[2*nfp+1], ql[ks], kr + 2);
                    ldsm4(kr, rowOff + 8192u + (((uint32_t)(ks*32) + kColS) ^ swf));
                    mma16816(s[2*nfp],   qh[ks], kr);
                    mma16816(s[2*nfp+1], qh[ks], kr + 2);
                }
            }

            if (kt >= 2*qt) {
                const int key0 = kt*64;
#pragma unroll
                for (int nf = 0; nf < 8; nf++) {
                    int kc = key0 + nf*8 + 2*tig;
                    if (kc     > rloc0) s[nf][0] = -1e30f;
                    if (kc + 1 > rloc0) s[nf][1] = -1e30f;
                    if (kc     > rloc1) s[nf][2] = -1e30f;
                    if (kc + 1 > rloc1) s[nf][3] = -1e30f;
                }
            }

            float mx0 = -1e30f, mx1 = -1e30f;
#pragma unroll
            for (int nf = 0; nf < 8; nf++) {
                mx0 = fmaxf(mx0, fmaxf(s[nf][0], s[nf][1]));
                mx1 = fmaxf(mx1, fmaxf(s[nf][2], s[nf][3]));
            }
            mx0 = fmaxf(mx0, __shfl_xor_sync(0xffffffffu, mx0, 1));
            mx0 = fmaxf(mx0, __shfl_xor_sync(0xffffffffu, mx0, 2));
            mx1 = fmaxf(mx1, __shfl_xor_sync(0xffffffffu, mx1, 1));
            mx1 = fmaxf(mx1, __shfl_xor_sync(0xffffffffu, mx1, 2));
            float mn0 = fmaxf(m0, mx0), mn1 = fmaxf(m1, mx1);
            float a0 = __expf(m0 - mn0), a1 = __expf(m1 - mn1);
            m0 = mn0; m1 = mn1;
            float sum0 = 0.f, sum1 = 0.f;
#pragma unroll
            for (int nf = 0; nf < 8; nf++) {
                s[nf][0] = __expf(s[nf][0] - mn0);
                s[nf][1] = __expf(s[nf][1] - mn0);
                s[nf][2] = __expf(s[nf][2] - mn1);
                s[nf][3] = __expf(s[nf][3] - mn1);
                sum0 += s[nf][0] + s[nf][1];
                sum1 += s[nf][2] + s[nf][3];
            }
            sum0 += __shfl_xor_sync(0xffffffffu, sum0, 1);
            sum0 += __shfl_xor_sync(0xffffffffu, sum0, 2);
            sum1 += __shfl_xor_sync(0xffffffffu, sum1, 1);
            sum1 += __shfl_xor_sync(0xffffffffu, sum1, 2);
            l0 = l0*a0 + sum0;
            l1 = l1*a1 + sum1;
#pragma unroll
            for (int nf = 0; nf < 8; nf++) {
                o[nf][0] *= a0; o[nf][1] *= a0;
                o[nf][2] *= a1; o[nf][3] *= a1;
            }

            // O += (Ph + Pl) @ Vh
#pragma unroll
            for (int sk = 0; sk < 4; sk++) {
                uint32_t ph[4], pl[4];
                split2(make_float2(s[2*sk][0],   s[2*sk][1]),   ph[0], pl[0]);
                split2(make_float2(s[2*sk][2],   s[2*sk][3]),   ph[1], pl[1]);
                split2(make_float2(s[2*sk+1][0], s[2*sk+1][1]), ph[2], pl[2]);
                split2(make_float2(s[2*sk+1][2], s[2*sk+1][3]), ph[3], pl[3]);
                const uint32_t vOff = bufB + 16384u + vRowB + (uint32_t)(sk*2048);
#pragma unroll
                for (int nb = 0; nb < 4; nb++) {
                    uint32_t vh4[4];
                    uint32_t co = (((uint32_t)(nb*32) + vColS) ^ swf);
                    ldsm4t(vh4, vOff + co);
                    mma16816(o[2*nb],   ph, vh4);
                    mma16816(o[2*nb+1], ph, vh4 + 2);
                    mma16816(o[2*nb],   pl, vh4);
                    mma16816(o[2*nb+1], pl, vh4 + 2);
                }
            }
        }
    }

    {
        float i0 = 1.f / l0, i1 = 1.f / l1;
        __half* base0 = gHs + (size_t)(b*SS + rloc0) * 1024;
        __half* base1 = gHs + (size_t)(b*SS + rloc1) * 1024;
#pragma unroll
        for (int nf = 0; nf < 8; nf++) {
            int col = h*64 + nf*8 + 2*tig;
            uint32_t hi, lo;
            split2(make_float2(o[nf][0]*i0, o[nf][1]*i0), hi, lo);
            *(uint32_t*)&base0[col]       = hi;
            *(uint32_t*)&base0[512 + col] = lo;
            split2(make_float2(o[nf][2]*i1, o[nf][3]*i1), hi, lo);
            *(uint32_t*)&base1[col]       = hi;
            *(uint32_t*)&base1[512 + col] = lo;
        }
    }
#undef LOAD_TILE
}

// ---------------------------------------------------------------------------
extern "C" void kernel_launch(void* const* d_in, const int* in_sizes, int n_in,
                              void* d_out, int out_size)
{
    const float* xs  = (const float*)d_in[0];
    const float* xt  = (const float*)d_in[1];
    const float* Wqs = (const float*)d_in[2];
    const float* Wks = (const float*)d_in[3];
    const float* Wvs = (const float*)d_in[4];
    const float* Wqt = (const float*)d_in[5];
    const float* Wkt = (const float*)d_in[6];
    const float* Wvt = (const float*)d_in[7];
    const float* WKb = (const float*)d_in[8];
    const float* Wo  = (const float*)d_in[9];
    float* out = (float*)d_out;

    const int GEMM_SMEM = 3 * 32768;      // 98304
    const int ATTN_SMEM = 2 * 24576;      // 49152
    cudaFuncSetAttribute(mma_gemm, cudaFuncAttributeMaxDynamicSharedMemorySize, GEMM_SMEM);
    cudaFuncSetAttribute(attn_mma, cudaFuncAttributeMaxDynamicSharedMemorySize, ATTN_SMEM);

    prep_all<<<PREPA_BLKS + PREPW_BLKS, 256>>>(xs, xt, Wqs, Wks, Wvs, Wqt, Wkt, Wvt);
    prep_Wo2<<<PREPWO_BLKS, 256>>>(Wo);

    mma_gemm<<<dim3(4, 64, 3), 256, GEMM_SMEM>>>(0, nullptr, WKb);
    attn_mma<<<512, 256, ATTN_SMEM>>>();
    mma_gemm<<<dim3(4, 64, 1), 256, GEMM_SMEM>>>(1, out, WKb);
}

// round 10
// speedup vs baseline: 1.2349x; 1.0099x over previous
#include <cuda_runtime.h>
#include <cuda_fp16.h>
#include <cstdint>

#define BB 8
#define SS 1024
#define DD 512
#define NHEADS 8
#define DHEAD 64
#define MROWS (BB*SS)   // 8192

// ---------------- scratch (no allocation allowed) ----------------
// fp16 split planes: [Qh|Ql|Kh|Kl|Vh], each [B*H][S][64]
#define PLANE ((size_t)4194304)
__device__ __half gP[5*PLANE];
__device__ __half gA[(size_t)MROWS*2048];       // [xs_h | xt_h | xs_l | xt_l]
__device__ __half gHs[(size_t)MROWS*1024];      // [H_h | H_l]
__device__ __half gBt[(size_t)3*512*2048];      // per-z W^T k-blocks [W1h,W2h,W1h,W2h]
__device__ __half gWoT[(size_t)512*1024];       // Wo^T k-blocks [Woh,Woh]

// ---------------- warp-mma helpers ----------------
__device__ __forceinline__ void ldsm4(uint32_t* r, uint32_t addr)
{
    asm volatile("ldmatrix.sync.aligned.m8n8.x4.shared.b16 {%0,%1,%2,%3}, [%4];"
        : "=r"(r[0]), "=r"(r[1]), "=r"(r[2]), "=r"(r[3]) : "r"(addr));
}

__device__ __forceinline__ void ldsm4t(uint32_t* r, uint32_t addr)
{
    asm volatile("ldmatrix.sync.aligned.m8n8.x4.trans.shared.b16 {%0,%1,%2,%3}, [%4];"
        : "=r"(r[0]), "=r"(r[1]), "=r"(r[2]), "=r"(r[3]) : "r"(addr));
}

__device__ __forceinline__ void mma16816(float* c, const uint32_t* a, const uint32_t* b)
{
    asm volatile(
        "mma.sync.aligned.m16n8k16.row.col.f32.f16.f16.f32 "
        "{%0,%1,%2,%3}, {%4,%5,%6,%7}, {%8,%9}, {%0,%1,%2,%3};"
        : "+f"(c[0]), "+f"(c[1]), "+f"(c[2]), "+f"(c[3])
        : "r"(a[0]), "r"(a[1]), "r"(a[2]), "r"(a[3]), "r"(b[0]), "r"(b[1]));
}

__device__ __forceinline__ void split2(float2 v, uint32_t& hi, uint32_t& lo)
{
    __half hx = __float2half_rn(v.x);
    __half hy = __float2half_rn(v.y);
    float rx = v.x - __half2float(hx);
    float ry = v.y - __half2float(hy);
    hi = ((uint32_t)__half_as_ushort(hy) << 16) | (uint32_t)__half_as_ushort(hx);
    lo = ((uint32_t)__half_as_ushort(__float2half_rn(ry)) << 16)
       | (uint32_t)__half_as_ushort(__float2half_rn(rx));
}

// ---------------------------------------------------------------------------
// fused prep kernel: A split + W pack + Wo pack, one launch
// ---------------------------------------------------------------------------
#define PREPA_BLKS 16384
#define PREPW_BLKS 12288
#define PREPWO_BLKS 2048

__global__ void prep_all(const float* __restrict__ xs, const float* __restrict__ xt,
                         const float* __restrict__ Wqs, const float* __restrict__ Wks,
                         const float* __restrict__ Wvs, const float* __restrict__ Wqt,
                         const float* __restrict__ Wkt, const float* __restrict__ Wvt,
                         const float* __restrict__ Wo)
{
    int bid = blockIdx.x;
    int tid = threadIdx.x;
    if (bid < PREPA_BLKS) {
        int r = bid >> 1;
        int c = (bid & 1) * 256 + tid;
        float a = xs[(size_t)r*DD + c];
        float b = xt[(size_t)r*DD + c];
        __half ah = __float2half_rn(a);
        __half bh = __float2half_rn(b);
        __half* row = gA + (size_t)r*2048;
        row[c]        = ah;
        row[512 + c]  = bh;
        row[1024 + c] = __float2half_rn(a - __half2float(ah));
        row[1536 + c] = __float2half_rn(b - __half2float(bh));
    } else if (bid < PREPA_BLKS + PREPW_BLKS) {
        int idx = (bid - PREPA_BLKS) * 256 + tid;     // 3*512*2048
        int z   = idx / (512*2048);
        int rem = idx % (512*2048);
        int n   = rem / 2048;
        int k   = rem % 2048;
        const float* W1 = (z==0) ? Wqs : ((z==1) ? Wks : Wvs);
        const float* W2 = (z==0) ? Wqt : ((z==1) ? Wkt : Wvt);
        int kh = k >> 9, ks = k & 511;
        const float* M = (kh & 1) ? W2 : W1;
        gBt[idx] = __float2half_rn(M[(size_t)ks*DD + n]);
    } else {
        int idx = (bid - PREPA_BLKS - PREPW_BLKS) * 256 + tid;  // 512*1024
        int n = idx / 1024;
        int k = idx % 1024;
        int ks = k & 511;
        gWoT[idx] = __float2half_rn(Wo[(size_t)ks*DD + n]);
    }
}

// ---------------------------------------------------------------------------
// fp16 mma.sync GEMM: 256 threads, 8 warps (2x4), warp tile 64x32,
// block 128x128, BK=64, 3-stage cp.async, SW128 swizzle, 1 sync/chunk.
// mode 0: QKV -> fp16 hi/lo planes gP (V: hi-only, lo K-chunks skipped)
// mode 1: OUT -> fp32 outp
// ---------------------------------------------------------------------------
__global__ __launch_bounds__(256)
void mma_gemm(int mode, float* __restrict__ outp, const float* __restrict__ WKb)
{
    extern __shared__ __half smg[];

    const __half* A;
    const __half* Bt;
    int aW, kEff, nChunks;
    const int z = blockIdx.z;
    if (mode == 0) {
        A = gA; aW = 2048; kEff = 2048;
        nChunks = (z == 2) ? 16 : 32;     // V: skip lo residual chunks
        Bt = gBt + (size_t)z * 512 * 2048;
    } else {
        A = gHs; aW = 1024; kEff = 1024; nChunks = 16;
        Bt = gWoT;
    }

    const int mBase = blockIdx.y * 128;
    const int nBase = blockIdx.x * 128;
    const int t    = threadIdx.x;
    const int warp = t >> 5;
    const int lane = t & 31;
    const int wm   = warp >> 2;
    const int wn   = warp & 3;

    const uint32_t sBase = (uint32_t)__cvta_generic_to_shared(smg);

    const int ldRow = t >> 3;
    const int ldSeg = t & 7;
    const uint32_t ldSw = ((uint32_t)ldRow << 7)
                        + (((uint32_t)ldSeg << 4) ^ (((uint32_t)ldRow & 7) << 4));

    float acc[4][4][4];
#pragma unroll
    for (int i = 0; i < 4; i++)
#pragma unroll
        for (int j = 0; j < 4; j++)
#pragma unroll
            for (int q = 0; q < 4; q++) acc[i][j][q] = 0.f;

#define LOAD_CHUNK(cc, buf) do { \
    const __half* Ag_ = A + (size_t)(mBase + ldRow) * aW + ((cc) << 6) + ldSeg * 8; \
    const __half* Bg_ = Bt + (size_t)(nBase + ldRow) * kEff + (size_t)(cc) * 64 + ldSeg * 8; \
    uint32_t da_ = sBase + (buf)*32768u + ldSw; \
    uint32_t db_ = da_ + 16384u; \
    _Pragma("unroll") \
    for (int rr_ = 0; rr_ < 4; rr_++) { \
        asm volatile("cp.async.cg.shared.global [%0], [%1], 16;" \
            :: "r"(da_ + rr_*4096u), "l"(__cvta_generic_to_global((const void*)(Ag_ + (size_t)rr_*32*aW)))); \
        asm volatile("cp.async.cg.shared.global [%0], [%1], 16;" \
            :: "r"(db_ + rr_*4096u), "l"(__cvta_generic_to_global((const void*)(Bg_ + (size_t)rr_*32*kEff)))); \
    } \
    asm volatile("cp.async.commit_group;" ::: "memory"); \
} while (0)

    LOAD_CHUNK(0, 0);
    LOAD_CHUNK(1, 1);

    const int aRowL = wm*64 + (lane & 15);
    const int aColB = (((lane >> 4) << 3)) * 2;
    const uint32_t aSw = ((uint32_t)aRowL & 7) << 4;
    const int bRowL = wn*32 + ((lane >> 4) << 3) + (lane & 7);
    const int bColB = ((((lane >> 3) & 1) << 3)) * 2;
    const uint32_t bSw = ((uint32_t)bRowL & 7) << 4;

    for (int c = 0; c < nChunks; c++) {
        const int buf = c % 3;
        if (c + 1 < nChunks) { asm volatile("cp.async.wait_group 1;" ::: "memory"); }
        else                 { asm volatile("cp.async.wait_group 0;" ::: "memory"); }
        __syncthreads();
        if (c + 2 < nChunks) LOAD_CHUNK(c + 2, (c + 2) % 3);

        const uint32_t aB = sBase + buf*32768u;
        const uint32_t bB = aB + 16384u;
#pragma unroll
        for (int ks = 0; ks < 4; ks++) {
            const uint32_t kb = (uint32_t)(ks << 5);
            uint32_t afr[4][4];
#pragma unroll
            for (int mf = 0; mf < 4; mf++)
                ldsm4(afr[mf], aB + (uint32_t)((aRowL + mf*16) << 7) + ((kb + aColB) ^ aSw));
            uint32_t bfr[4][2];
#pragma unroll
            for (int nfp = 0; nfp < 2; nfp++) {
                uint32_t r4[4];
                ldsm4(r4, bB + (uint32_t)((bRowL + nfp*16) << 7) + ((kb + bColB) ^ bSw));
                bfr[nfp*2+0][0] = r4[0]; bfr[nfp*2+0][1] = r4[1];
                bfr[nfp*2+1][0] = r4[2]; bfr[nfp*2+1][1] = r4[3];
            }
#pragma unroll
            for (int mf = 0; mf < 4; mf++)
#pragma unroll
                for (int nf = 0; nf < 4; nf++)
                    mma16816(acc[mf][nf], afr[mf], bfr[nf]);
        }
    }

    const int g   = lane >> 2;
    const int tig = lane & 3;

    if (mode == 0) {
        __half* Ph = gP + (size_t)((z==0) ? 0 : (z==1) ? 2 : 4) * PLANE;
        __half* Pl = Ph + PLANE;
#pragma unroll
        for (int mf = 0; mf < 4; mf++) {
            int row0 = mBase + wm*64 + mf*16 + g;
            int bb = row0 >> 10, s0 = row0 & (SS-1);
#pragma unroll
            for (int nf = 0; nf < 4; nf++) {
                int col = nBase + wn*32 + nf*8 + tig*2;
                int hh = col >> 6, d = col & 63;
                float c0 = acc[mf][nf][0], c1 = acc[mf][nf][1];
                float c2 = acc[mf][nf][2], c3 = acc[mf][nf][3];
                if (z == 0) { c0 *= 0.125f; c1 *= 0.125f; c2 *= 0.125f; c3 *= 0.125f; }
                else if (z == 1) {
                    c0 += WKb[d*SS + s0];       c1 += WKb[(d+1)*SS + s0];
                    c2 += WKb[d*SS + s0 + 8];   c3 += WKb[(d+1)*SS + s0 + 8];
                }
                size_t off0 = ((size_t)(bb*NHEADS + hh)*SS + s0)*64 + d;
                uint32_t hi, lo;
                split2(make_float2(c0, c1), hi, lo);
                *(uint32_t*)&Ph[off0] = hi;
                if (z < 2) *(uint32_t*)&Pl[off0] = lo;
                split2(make_float2(c2, c3), hi, lo);
                *(uint32_t*)&Ph[off0 + 512] = hi;
                if (z < 2) *(uint32_t*)&Pl[off0 + 512] = lo;
            }
        }
    } else {
#pragma unroll
        for (int mf = 0; mf < 4; mf++) {
            int row0 = mBase + wm*64 + mf*16 + g;
#pragma unroll
            for (int nf = 0; nf < 4; nf++) {
                int col = nBase + wn*32 + nf*8 + tig*2;
                *(float2*)&outp[(size_t)row0*DD + col]
                    = make_float2(acc[mf][nf][0], acc[mf][nf][1]);
                *(float2*)&outp[(size_t)(row0+8)*DD + col]
                    = make_float2(acc[mf][nf][2], acc[mf][nf][3]);
            }
        }
    }
#undef LOAD_CHUNK
}

// ---------------------------------------------------------------------------
// fp16 causal flash attention: q-tile 128 (8 warps x 16 rows), k-tile 64,
// scores 3-term, PV 2-term (Vh only), double-buffered smem, 1 sync/tile.
// __launch_bounds__(256, 2): cap regs at 128 for 2 CTAs/SM (live regs ~115).
// ---------------------------------------------------------------------------
__global__ __launch_bounds__(256, 2) void attn_mma()
{
    extern __shared__ __half sma[];

    const int bx = blockIdx.x;
    const int qt = 7 - (bx >> 6);
    const int bh = bx & 63;
    const int b = bh >> 3, h = bh & 7;
    const int t = threadIdx.x, warp = t >> 5, lane = t & 31;
    const int g = lane >> 2, tig = lane & 3;

    const size_t bhOff = (size_t)(b*NHEADS + h) * SS * 64;
    const __half* pQh = gP + bhOff;
    const __half* pQl = gP + PLANE   + bhOff;
    const __half* pKh = gP + 2*PLANE + bhOff;
    const __half* pKl = gP + 3*PLANE + bhOff;
    const __half* pVh = gP + 4*PLANE + bhOff;

    const int rloc0 = qt*128 + warp*16 + g;
    const int rloc1 = rloc0 + 8;

    uint32_t qh[4][4], ql[4][4];
    {
        const size_t q0 = (size_t)rloc0 * 64 + 2*tig;
        const size_t q1 = (size_t)rloc1 * 64 + 2*tig;
#pragma unroll
        for (int s = 0; s < 4; s++) {
            qh[s][0] = *(const uint32_t*)&pQh[q0 + s*16];
            qh[s][1] = *(const uint32_t*)&pQh[q1 + s*16];
            qh[s][2] = *(const uint32_t*)&pQh[q0 + s*16 + 8];
            qh[s][3] = *(const uint32_t*)&pQh[q1 + s*16 + 8];
            ql[s][0] = *(const uint32_t*)&pQl[q0 + s*16];
            ql[s][1] = *(const uint32_t*)&pQl[q1 + s*16];
            ql[s][2] = *(const uint32_t*)&pQl[q0 + s*16 + 8];
            ql[s][3] = *(const uint32_t*)&pQl[q1 + s*16 + 8];
        }
    }

    float o[8][4];
#pragma unroll
    for (int nf = 0; nf < 8; nf++)
#pragma unroll
        for (int j = 0; j < 4; j++) o[nf][j] = 0.f;
    float m0 = -1e30f, m1 = -1e30f, l0 = 0.f, l1 = 0.f;

    const uint32_t smB = (uint32_t)__cvta_generic_to_shared(sma);
    const int lr8 = t >> 2;
    const int ls  = t & 3;
    const uint32_t swst = ((uint32_t)lr8 & 7) << 4;

#define LOAD_TILE(kt_, buf_) do { \
    const size_t ro_ = (size_t)((kt_)*64 + lr8) * 64; \
    uint32_t db_ = smB + (uint32_t)((buf_)*24576) + (uint32_t)(lr8*128); \
    _Pragma("unroll") \
    for (int sg_ = 0; sg_ < 2; sg_++) { \
        int seg_ = ls*2 + sg_; \
        uint32_t co_ = ((uint32_t)(seg_*16)) ^ swst; \
        asm volatile("cp.async.cg.shared.global [%0], [%1], 16;" \
            :: "r"(db_ + co_),          "l"(__cvta_generic_to_global((const void*)(pKh + ro_ + seg_*8)))); \
        asm volatile("cp.async.cg.shared.global [%0], [%1], 16;" \
            :: "r"(db_ + 8192u + co_),  "l"(__cvta_generic_to_global((const void*)(pKl + ro_ + seg_*8)))); \
        asm volatile("cp.async.cg.shared.global [%0], [%1], 16;" \
            :: "r"(db_ + 16384u + co_), "l"(__cvta_generic_to_global((const void*)(pVh + ro_ + seg_*8)))); \
    } \
    asm volatile("cp.async.commit_group;" ::: "memory"); \
} while (0)

    const uint32_t swf = (uint32_t)(lane & 7) << 4;
    const uint32_t kRowB = (uint32_t)((((lane>>4)<<3) | (lane&7)) * 128);
    const uint32_t kColS = (uint32_t)(((lane>>3)&1) << 4);
    const uint32_t vRowB = (uint32_t)((lane & 15) * 128);
    const uint32_t vColS = (uint32_t)((lane>>4) << 4);

    const int nkt = 2*qt + 2;
    LOAD_TILE(0, 0);

    for (int kt = 0; kt < nkt; kt++) {
        asm volatile("cp.async.wait_group 0;" ::: "memory");
        __syncthreads();
        if (kt + 1 < nkt) LOAD_TILE(kt + 1, (kt + 1) & 1);

        const uint32_t bufB = smB + (uint32_t)((kt & 1) * 24576);
        const bool active = (qt*128 + warp*16 + 15) >= kt*64;
        if (active) {
            float s[8][4];
#pragma unroll
            for (int nf = 0; nf < 8; nf++)
#pragma unroll
                for (int j = 0; j < 4; j++) s[nf][j] = 0.f;

#pragma unroll
            for (int nfp = 0; nfp < 4; nfp++) {
                const uint32_t rowOff = bufB + kRowB + (uint32_t)(nfp*2048);
#pragma unroll
                for (int ks = 0; ks < 4; ks++) {
                    uint32_t kr[4];
                    ldsm4(kr, rowOff + (((uint32_t)(ks*32) + kColS) ^ swf));
                    mma16816(s[2*nfp],   qh[ks], kr);
                    mma16816(s[2*nfp+1], qh[ks], kr + 2);
                    mma16816(s[2*nfp],   ql[ks], kr);
                    mma16816(s[2*nfp+1], ql[ks], kr + 2);
                    ldsm4(kr, rowOff + 8192u + (((uint32_t)(ks*32) + kColS) ^ swf));
                    mma16816(s[2*nfp],   qh[ks], kr);
                    mma16816(s[2*nfp+1], qh[ks], kr + 2);
                }
            }

            if (kt >= 2*qt) {
                const int key0 = kt*64;
#pragma unroll
                for (int nf = 0; nf < 8; nf++) {
                    int kc = key0 + nf*8 + 2*tig;
                    if (kc     > rloc0) s[nf][0] = -1e30f;
                    if (kc + 1 > rloc0) s[nf][1] = -1e30f;
                    if (kc     > rloc1) s[nf][2] = -1e30f;
                    if (kc + 1 > rloc1) s[nf][3] = -1e30f;
                }
            }

            float mx0 = -1e30f, mx1 = -1e30f;
#pragma unroll
            for (int nf = 0; nf < 8; nf++) {
                mx0 = fmaxf(mx0, fmaxf(s[nf][0], s[nf][1]));
                mx1 = fmaxf(mx1, fmaxf(s[nf][2], s[nf][3]));
            }
            mx0 = fmaxf(mx0, __shfl_xor_sync(0xffffffffu, mx0, 1));
            mx0 = fmaxf(mx0, __shfl_xor_sync(0xffffffffu, mx0, 2));
            mx1 = fmaxf(mx1, __shfl_xor_sync(0xffffffffu, mx1, 1));
            mx1 = fmaxf(mx1, __shfl_xor_sync(0xffffffffu, mx1, 2));
            float mn0 = fmaxf(m0, mx0), mn1 = fmaxf(m1, mx1);
            float a0 = __expf(m0 - mn0), a1 = __expf(m1 - mn1);
            m0 = mn0; m1 = mn1;
            float sum0 = 0.f, sum1 = 0.f;
#pragma unroll
            for (int nf = 0; nf < 8; nf++) {
                s[nf][0] = __expf(s[nf][0] - mn0);
                s[nf][1] = __expf(s[nf][1] - mn0);
                s[nf][2] = __expf(s[nf][2] - mn1);
                s[nf][3] = __expf(s[nf][3] - mn1);
                sum0 += s[nf][0] + s[nf][1];
                sum1 += s[nf][2] + s[nf][3];
            }
            sum0 += __shfl_xor_sync(0xffffffffu, sum0, 1);
            sum0 += __shfl_xor_sync(0xffffffffu, sum0, 2);
            sum1 += __shfl_xor_sync(0xffffffffu, sum1, 1);
            sum1 += __shfl_xor_sync(0xffffffffu, sum1, 2);
            l0 = l0*a0 + sum0;
            l1 = l1*a1 + sum1;
#pragma unroll
            for (int nf = 0; nf < 8; nf++) {
                o[nf][0] *= a0; o[nf][1] *= a0;
                o[nf][2] *= a1; o[nf][3] *= a1;
            }

            // O += (Ph + Pl) @ Vh
#pragma unroll
            for (int sk = 0; sk < 4; sk++) {
                uint32_t ph[4], pl[4];
                split2(make_float2(s[2*sk][0],   s[2*sk][1]),   ph[0], pl[0]);
                split2(make_float2(s[2*sk][2],   s[2*sk][3]),   ph[1], pl[1]);
                split2(make_float2(s[2*sk+1][0], s[2*sk+1][1]), ph[2], pl[2]);
                split2(make_float2(s[2*sk+1][2], s[2*sk+1][3]), ph[3], pl[3]);
                const uint32_t vOff = bufB + 16384u + vRowB + (uint32_t)(sk*2048);
#pragma unroll
                for (int nb = 0; nb < 4; nb++) {
                    uint32_t vh4[4];
                    uint32_t co = (((uint32_t)(nb*32) + vColS) ^ swf);
                    ldsm4t(vh4, vOff + co);
                    mma16816(o[2*nb],   ph, vh4);
                    mma16816(o[2*nb+1], ph, vh4 + 2);
                    mma16816(o[2*nb],   pl, vh4);
                    mma16816(o[2*nb+1], pl, vh4 + 2);
                }
            }
        }
    }

    {
        float i0 = 1.f / l0, i1 = 1.f / l1;
        __half* base0 = gHs + (size_t)(b*SS + rloc0) * 1024;
        __half* base1 = gHs + (size_t)(b*SS + rloc1) * 1024;
#pragma unroll
        for (int nf = 0; nf < 8; nf++) {
            int col = h*64 + nf*8 + 2*tig;
            uint32_t hi, lo;
            split2(make_float2(o[nf][0]*i0, o[nf][1]*i0), hi, lo);
            *(uint32_t*)&base0[col]       = hi;
            *(uint32_t*)&base0[512 + col] = lo;
            split2(make_float2(o[nf][2]*i1, o[nf][3]*i1), hi, lo);
            *(uint32_t*)&base1[col]       = hi;
            *(uint32_t*)&base1[512 + col] = lo;
        }
    }
#undef LOAD_TILE
}

// ---------------------------------------------------------------------------
extern "C" void kernel_launch(void* const* d_in, const int* in_sizes, int n_in,
                              void* d_out, int out_size)
{
    const float* xs  = (const float*)d_in[0];
    const float* xt  = (const float*)d_in[1];
    const float* Wqs = (const float*)d_in[2];
    const float* Wks = (const float*)d_in[3];
    const float* Wvs = (const float*)d_in[4];
    const float* Wqt = (const float*)d_in[5];
    const float* Wkt = (const float*)d_in[6];
    const float* Wvt = (const float*)d_in[7];
    const float* WKb = (const float*)d_in[8];
    const float* Wo  = (const float*)d_in[9];
    float* out = (float*)d_out;

    const int GEMM_SMEM = 3 * 32768;      // 98304
    const int ATTN_SMEM = 2 * 24576;      // 49152
    cudaFuncSetAttribute(mma_gemm, cudaFuncAttributeMaxDynamicSharedMemorySize, GEMM_SMEM);
    cudaFuncSetAttribute(attn_mma, cudaFuncAttributeMaxDynamicSharedMemorySize, ATTN_SMEM);

    prep_all<<<PREPA_BLKS + PREPW_BLKS + PREPWO_BLKS, 256>>>(
        xs, xt, Wqs, Wks, Wvs, Wqt, Wkt, Wvt, Wo);

    mma_gemm<<<dim3(4, 64, 3), 256, GEMM_SMEM>>>(0, nullptr, WKb);
    attn_mma<<<512, 256, ATTN_SMEM>>>();
    mma_gemm<<<dim3(4, 64, 1), 256, GEMM_SMEM>>>(1, out, WKb);
}

// round 11
// speedup vs baseline: 1.3574x; 1.0992x over previous
#include <cuda_runtime.h>
#include <cuda_fp16.h>
#include <cstdint>

#define BB 8
#define SS 1024
#define DD 512
#define NHEADS 8
#define DHEAD 64
#define MROWS (BB*SS)   // 8192

// ---------------- scratch (no allocation allowed) ----------------
// fp16 split planes: [Qh|Ql|Kh|Kl|Vh], each [B*H][S][64]
#define PLANE ((size_t)4194304)
__device__ __half gP[5*PLANE];
__device__ __half gA[(size_t)MROWS*2048];       // [xs_h | xt_h | xs_l | xt_l]
__device__ __half gHs[(size_t)MROWS*1024];      // [H_h | H_l]
__device__ __half gBt[(size_t)3*512*1024];      // per-z W^T, k = [W1h(512)|W2h(512)]
__device__ __half gWoT[(size_t)512*512];        // Wo^T

// ---------------- warp-mma helpers ----------------
__device__ __forceinline__ void ldsm4(uint32_t* r, uint32_t addr)
{
    asm volatile("ldmatrix.sync.aligned.m8n8.x4.shared.b16 {%0,%1,%2,%3}, [%4];"
        : "=r"(r[0]), "=r"(r[1]), "=r"(r[2]), "=r"(r[3]) : "r"(addr));
}

__device__ __forceinline__ void ldsm4t(uint32_t* r, uint32_t addr)
{
    asm volatile("ldmatrix.sync.aligned.m8n8.x4.trans.shared.b16 {%0,%1,%2,%3}, [%4];"
        : "=r"(r[0]), "=r"(r[1]), "=r"(r[2]), "=r"(r[3]) : "r"(addr));
}

__device__ __forceinline__ void mma16816(float* c, const uint32_t* a, const uint32_t* b)
{
    asm volatile(
        "mma.sync.aligned.m16n8k16.row.col.f32.f16.f16.f32 "
        "{%0,%1,%2,%3}, {%4,%5,%6,%7}, {%8,%9}, {%0,%1,%2,%3};"
        : "+f"(c[0]), "+f"(c[1]), "+f"(c[2]), "+f"(c[3])
        : "r"(a[0]), "r"(a[1]), "r"(a[2]), "r"(a[3]), "r"(b[0]), "r"(b[1]));
}

__device__ __forceinline__ void split2(float2 v, uint32_t& hi, uint32_t& lo)
{
    __half hx = __float2half_rn(v.x);
    __half hy = __float2half_rn(v.y);
    float rx = v.x - __half2float(hx);
    float ry = v.y - __half2float(hy);
    hi = ((uint32_t)__half_as_ushort(hy) << 16) | (uint32_t)__half_as_ushort(hx);
    lo = ((uint32_t)__half_as_ushort(__float2half_rn(ry)) << 16)
       | (uint32_t)__half_as_ushort(__float2half_rn(rx));
}

// ---------------------------------------------------------------------------
// fused prep: [0,4096) A-split float4; [4096,4480) W transpose-pack (z 0..2);
// [4480,4544) Wo transpose-pack
// ---------------------------------------------------------------------------
__global__ void prep_all(const float* __restrict__ xs, const float* __restrict__ xt,
                         const float* __restrict__ Wqs, const float* __restrict__ Wks,
                         const float* __restrict__ Wvs, const float* __restrict__ Wqt,
                         const float* __restrict__ Wkt, const float* __restrict__ Wvt,
                         const float* __restrict__ Wo)
{
    __shared__ __half smt[64*65];
    const int bid = blockIdx.x;
    const int t = threadIdx.x;

    if (bid < 4096) {
        int idx = bid*256 + t;
        int r = idx >> 7;
        int c = (idx & 127) << 2;
        float4 a = *(const float4*)&xs[(size_t)r*DD + c];
        float4 b = *(const float4*)&xt[(size_t)r*DD + c];
        __half* row = gA + (size_t)r*2048;
        uint32_t h0, l0, h1, l1;
        split2(make_float2(a.x, a.y), h0, l0);
        split2(make_float2(a.z, a.w), h1, l1);
        *(uint2*)&row[c]        = make_uint2(h0, h1);
        *(uint2*)&row[1024 + c] = make_uint2(l0, l1);
        split2(make_float2(b.x, b.y), h0, l0);
        split2(make_float2(b.z, b.w), h1, l1);
        *(uint2*)&row[512 + c]  = make_uint2(h0, h1);
        *(uint2*)&row[1536 + c] = make_uint2(l0, l1);
        return;
    }

    int wb = bid - 4096;
    const float* src;
    __half* dst;
    int stride, n0, kbase, ks0;
    if (wb < 384) {
        int z = wb >> 7, rem = wb & 127;
        int ntile = rem >> 4, ktile = rem & 15;
        const float* W1 = (z==0) ? Wqs : ((z==1) ? Wks : Wvs);
        const float* W2 = (z==0) ? Wqt : ((z==1) ? Wkt : Wvt);
        src = (ktile < 8) ? W1 : W2;
        ks0 = (ktile & 7) * 64;
        dst = gBt + (size_t)z * 512 * 1024;
        stride = 1024;
        n0 = ntile * 64;
        kbase = ktile * 64;
    } else {
        int rem = wb - 384;
        int ntile = rem >> 3, ktile = rem & 7;
        src = Wo;
        ks0 = ktile * 64;
        dst = gWoT;
        stride = 512;
        n0 = ntile * 64;
        kbase = ktile * 64;
    }

    {   // coalesced read of 64x64 fp32 tile -> smem (as half), [k][n]
        int cc = t & 63, rr = t >> 6;
#pragma unroll
        for (int i = 0; i < 16; i++) {
            int row = rr*16 + i;
            smt[row*65 + cc] = __float2half_rn(src[(size_t)(ks0 + row)*DD + n0 + cc]);
        }
    }
    __syncthreads();
    {   // coalesced write: dst[n][k] rows of 64 halves
        int kc = (t & 31) * 2, rn = t >> 5;
#pragma unroll
        for (int i = 0; i < 8; i++) {
            int nl = rn + i*8;
            uint32_t v = ((uint32_t)__half_as_ushort(smt[(kc+1)*65 + nl]) << 16)
                       |  (uint32_t)__half_as_ushort(smt[kc*65 + nl]);
            *(uint32_t*)&dst[(size_t)(n0 + nl)*stride + kbase + kc] = v;
        }
    }
}

// ---------------------------------------------------------------------------
// fp16 mma.sync GEMM: 256 threads, 8 warps (2x4), warp tile 64x32,
// block 128x128. Per chunk: ONE B tile (64 k) + A-hi + A-lo tiles; bfr reused
// across both A-terms. 2-stage double buffer (48KB/stage), SW128 swizzle.
// mode 0: QKV -> fp16 hi/lo planes gP (V: A-hi only); mode 1: OUT -> fp32
// ---------------------------------------------------------------------------
__global__ __launch_bounds__(256)
void mma_gemm(int mode, float* __restrict__ outp, const float* __restrict__ WKb)
{
    extern __shared__ __half smg[];

    const __half* A;
    const __half* Bt;
    int aW, bStride, nChunks, aLoOff, nAt;
    const int z = blockIdx.z;
    if (mode == 0) {
        A = gA; aW = 2048; bStride = 1024; nChunks = 16; aLoOff = 1024;
        nAt = (z == 2) ? 1 : 2;
        Bt = gBt + (size_t)z * 512 * 1024;
    } else {
        A = gHs; aW = 1024; bStride = 512; nChunks = 8; aLoOff = 512;
        nAt = 2;
        Bt = gWoT;
    }

    const int mBase = blockIdx.y * 128;
    const int nBase = blockIdx.x * 128;
    const int t    = threadIdx.x;
    const int warp = t >> 5;
    const int lane = t & 31;
    const int wm   = warp >> 2;
    const int wn   = warp & 3;

    const uint32_t sBase = (uint32_t)__cvta_generic_to_shared(smg);

    const int ldRow = t >> 3;
    const int ldSeg = t & 7;
    const uint32_t ldSw = ((uint32_t)ldRow << 7)
                        + (((uint32_t)ldSeg << 4) ^ (((uint32_t)ldRow & 7) << 4));

    float acc[4][4][4];
#pragma unroll
    for (int i = 0; i < 4; i++)
#pragma unroll
        for (int j = 0; j < 4; j++)
#pragma unroll
            for (int q = 0; q < 4; q++) acc[i][j][q] = 0.f;

// stage layout: Ahi [0,16K), Alo [16K,32K), B [32K,48K)
#define LOAD_CHUNK(cc, buf) do { \
    const __half* Ah_ = A + (size_t)(mBase + ldRow) * aW + ((cc) << 6) + ldSeg * 8; \
    const __half* Bg_ = Bt + (size_t)(nBase + ldRow) * bStride + ((cc) << 6) + ldSeg * 8; \
    uint32_t base_ = sBase + (buf)*49152u + ldSw; \
    _Pragma("unroll") \
    for (int rr_ = 0; rr_ < 4; rr_++) { \
        asm volatile("cp.async.cg.shared.global [%0], [%1], 16;" \
            :: "r"(base_ + rr_*4096u), \
               "l"(__cvta_generic_to_global((const void*)(Ah_ + (size_t)rr_*32*aW)))); \
        if (nAt == 2) \
            asm volatile("cp.async.cg.shared.global [%0], [%1], 16;" \
                :: "r"(base_ + 16384u + rr_*4096u), \
                   "l"(__cvta_generic_to_global((const void*)(Ah_ + aLoOff + (size_t)rr_*32*aW)))); \
        asm volatile("cp.async.cg.shared.global [%0], [%1], 16;" \
            :: "r"(base_ + 32768u + rr_*4096u), \
               "l"(__cvta_generic_to_global((const void*)(Bg_ + (size_t)rr_*32*bStride)))); \
    } \
    asm volatile("cp.async.commit_group;" ::: "memory"); \
} while (0)

    LOAD_CHUNK(0, 0);
    LOAD_CHUNK(1, 1);

    const int aRowL = wm*64 + (lane & 15);
    const int aColB = (((lane >> 4) << 3)) * 2;
    const uint32_t aSw = ((uint32_t)aRowL & 7) << 4;
    const int bRowL = wn*32 + ((lane >> 4) << 3) + (lane & 7);
    const int bColB = ((((lane >> 3) & 1) << 3)) * 2;
    const uint32_t bSw = ((uint32_t)bRowL & 7) << 4;

    for (int c = 0; c < nChunks; c++) {
        if (c + 1 < nChunks) { asm volatile("cp.async.wait_group 1;" ::: "memory"); }
        else                 { asm volatile("cp.async.wait_group 0;" ::: "memory"); }
        __syncthreads();

        const uint32_t stg = sBase + (uint32_t)((c & 1) * 49152);
        const uint32_t bB  = stg + 32768u;
#pragma unroll
        for (int ks = 0; ks < 4; ks++) {
            const uint32_t kb = (uint32_t)(ks << 5);
            uint32_t bfr[4][2];
#pragma unroll
            for (int nfp = 0; nfp < 2; nfp++) {
                uint32_t r4[4];
                ldsm4(r4, bB + (uint32_t)((bRowL + nfp*16) << 7) + ((kb + bColB) ^ bSw));
                bfr[nfp*2+0][0] = r4[0]; bfr[nfp*2+0][1] = r4[1];
                bfr[nfp*2+1][0] = r4[2]; bfr[nfp*2+1][1] = r4[3];
            }
#pragma unroll
            for (int at = 0; at < 2; at++) {
                if (at == 1 && nAt == 1) break;
                const uint32_t aB = stg + (uint32_t)(at * 16384);
                uint32_t afr[4][4];
#pragma unroll
                for (int mf = 0; mf < 4; mf++)
                    ldsm4(afr[mf], aB + (uint32_t)((aRowL + mf*16) << 7) + ((kb + aColB) ^ aSw));
#pragma unroll
                for (int mf = 0; mf < 4; mf++)
#pragma unroll
                    for (int nf = 0; nf < 4; nf++)
                        mma16816(acc[mf][nf], afr[mf], bfr[nf]);
            }
        }
        __syncthreads();
        if (c + 2 < nChunks) LOAD_CHUNK(c + 2, c & 1);
    }

    const int g   = lane >> 2;
    const int tig = lane & 3;

    if (mode == 0) {
        __half* Ph = gP + (size_t)((z==0) ? 0 : (z==1) ? 2 : 4) * PLANE;
        __half* Pl = Ph + PLANE;
#pragma unroll
        for (int mf = 0; mf < 4; mf++) {
            int row0 = mBase + wm*64 + mf*16 + g;
            int bb = row0 >> 10, s0 = row0 & (SS-1);
#pragma unroll
            for (int nf = 0; nf < 4; nf++) {
                int col = nBase + wn*32 + nf*8 + tig*2;
                int hh = col >> 6, d = col & 63;
                float c0 = acc[mf][nf][0], c1 = acc[mf][nf][1];
                float c2 = acc[mf][nf][2], c3 = acc[mf][nf][3];
                if (z == 0) { c0 *= 0.125f; c1 *= 0.125f; c2 *= 0.125f; c3 *= 0.125f; }
                else if (z == 1) {
                    c0 += WKb[d*SS + s0];       c1 += WKb[(d+1)*SS + s0];
                    c2 += WKb[d*SS + s0 + 8];   c3 += WKb[(d+1)*SS + s0 + 8];
                }
                size_t off0 = ((size_t)(bb*NHEADS + hh)*SS + s0)*64 + d;
                uint32_t hi, lo;
                split2(make_float2(c0, c1), hi, lo);
                *(uint32_t*)&Ph[off0] = hi;
                if (z < 2) *(uint32_t*)&Pl[off0] = lo;
                split2(make_float2(c2, c3), hi, lo);
                *(uint32_t*)&Ph[off0 + 512] = hi;
                if (z < 2) *(uint32_t*)&Pl[off0 + 512] = lo;
            }
        }
    } else {
#pragma unroll
        for (int mf = 0; mf < 4; mf++) {
            int row0 = mBase + wm*64 + mf*16 + g;
#pragma unroll
            for (int nf = 0; nf < 4; nf++) {
                int col = nBase + wn*32 + nf*8 + tig*2;
                *(float2*)&outp[(size_t)row0*DD + col]
                    = make_float2(acc[mf][nf][0], acc[mf][nf][1]);
                *(float2*)&outp[(size_t)(row0+8)*DD + col]
                    = make_float2(acc[mf][nf][2], acc[mf][nf][3]);
            }
        }
    }
#undef LOAD_CHUNK
}

// ---------------------------------------------------------------------------
// fp16 causal flash attention (unchanged, passing config): q-tile 128
// (8 warps x 16 rows), k-tile 64, scores 3-term, PV 2-term (Vh only),
// double-buffered smem, 1 sync/tile, __launch_bounds__(256, 2).
// ---------------------------------------------------------------------------
__global__ __launch_bounds__(256, 2) void attn_mma()
{
    extern __shared__ __half sma[];

    const int bx = blockIdx.x;
    const int qt = 7 - (bx >> 6);
    const int bh = bx & 63;
    const int b = bh >> 3, h = bh & 7;
    const int t = threadIdx.x, warp = t >> 5, lane = t & 31;
    const int g = lane >> 2, tig = lane & 3;

    const size_t bhOff = (size_t)(b*NHEADS + h) * SS * 64;
    const __half* pQh = gP + bhOff;
    const __half* pQl = gP + PLANE   + bhOff;
    const __half* pKh = gP + 2*PLANE + bhOff;
    const __half* pKl = gP + 3*PLANE + bhOff;
    const __half* pVh = gP + 4*PLANE + bhOff;

    const int rloc0 = qt*128 + warp*16 + g;
    const int rloc1 = rloc0 + 8;

    uint32_t qh[4][4], ql[4][4];
    {
        const size_t q0 = (size_t)rloc0 * 64 + 2*tig;
        const size_t q1 = (size_t)rloc1 * 64 + 2*tig;
#pragma unroll
        for (int s = 0; s < 4; s++) {
            qh[s][0] = *(const uint32_t*)&pQh[q0 + s*16];
            qh[s][1] = *(const uint32_t*)&pQh[q1 + s*16];
            qh[s][2] = *(const uint32_t*)&pQh[q0 + s*16 + 8];
            qh[s][3] = *(const uint32_t*)&pQh[q1 + s*16 + 8];
            ql[s][0] = *(const uint32_t*)&pQl[q0 + s*16];
            ql[s][1] = *(const uint32_t*)&pQl[q1 + s*16];
            ql[s][2] = *(const uint32_t*)&pQl[q0 + s*16 + 8];
            ql[s][3] = *(const uint32_t*)&pQl[q1 + s*16 + 8];
        }
    }

    float o[8][4];
#pragma unroll
    for (int nf = 0; nf < 8; nf++)
#pragma unroll
        for (int j = 0; j < 4; j++) o[nf][j] = 0.f;
    float m0 = -1e30f, m1 = -1e30f, l0 = 0.f, l1 = 0.f;

    const uint32_t smB = (uint32_t)__cvta_generic_to_shared(sma);
    const int lr8 = t >> 2;
    const int ls  = t & 3;
    const uint32_t swst = ((uint32_t)lr8 & 7) << 4;

#define LOAD_TILE(kt_, buf_) do { \
    const size_t ro_ = (size_t)((kt_)*64 + lr8) * 64; \
    uint32_t db_ = smB + (uint32_t)((buf_)*24576) + (uint32_t)(lr8*128); \
    _Pragma("unroll") \
    for (int sg_ = 0; sg_ < 2; sg_++) { \
        int seg_ = ls*2 + sg_; \
        uint32_t co_ = ((uint32_t)(seg_*16)) ^ swst; \
        asm volatile("cp.async.cg.shared.global [%0], [%1], 16;" \
            :: "r"(db_ + co_),          "l"(__cvta_generic_to_global((const void*)(pKh + ro_ + seg_*8)))); \
        asm volatile("cp.async.cg.shared.global [%0], [%1], 16;" \
            :: "r"(db_ + 8192u + co_),  "l"(__cvta_generic_to_global((const void*)(pKl + ro_ + seg_*8)))); \
        asm volatile("cp.async.cg.shared.global [%0], [%1], 16;" \
            :: "r"(db_ + 16384u + co_), "l"(__cvta_generic_to_global((const void*)(pVh + ro_ + seg_*8)))); \
    } \
    asm volatile("cp.async.commit_group;" ::: "memory"); \
} while (0)

    const uint32_t swf = (uint32_t)(lane & 7) << 4;
    const uint32_t kRowB = (uint32_t)((((lane>>4)<<3) | (lane&7)) * 128);
    const uint32_t kColS = (uint32_t)(((lane>>3)&1) << 4);
    const uint32_t vRowB = (uint32_t)((lane & 15) * 128);
    const uint32_t vColS = (uint32_t)((lane>>4) << 4);

    const int nkt = 2*qt + 2;
    LOAD_TILE(0, 0);

    for (int kt = 0; kt < nkt; kt++) {
        asm volatile("cp.async.wait_group 0;" ::: "memory");
        __syncthreads();
        if (kt + 1 < nkt) LOAD_TILE(kt + 1, (kt + 1) & 1);

        const uint32_t bufB = smB + (uint32_t)((kt & 1) * 24576);
        const bool active = (qt*128 + warp*16 + 15) >= kt*64;
        if (active) {
            float s[8][4];
#pragma unroll
            for (int nf = 0; nf < 8; nf++)
#pragma unroll
                for (int j = 0; j < 4; j++) s[nf][j] = 0.f;

#pragma unroll
            for (int nfp = 0; nfp < 4; nfp++) {
                const uint32_t rowOff = bufB + kRowB + (uint32_t)(nfp*2048);
#pragma unroll
                for (int ks = 0; ks < 4; ks++) {
                    uint32_t kr[4];
                    ldsm4(kr, rowOff + (((uint32_t)(ks*32) + kColS) ^ swf));
                    mma16816(s[2*nfp],   qh[ks], kr);
                    mma16816(s[2*nfp+1], qh[ks], kr + 2);
                    mma16816(s[2*nfp],   ql[ks], kr);
                    mma16816(s[2*nfp+1], ql[ks], kr + 2);
                    ldsm4(kr, rowOff + 8192u + (((uint32_t)(ks*32) + kColS) ^ swf));
                    mma16816(s[2*nfp],   qh[ks], kr);
                    mma16816(s[2*nfp+1], qh[ks], kr + 2);
                }
            }

            if (kt >= 2*qt) {
                const int key0 = kt*64;
#pragma unroll
                for (int nf = 0; nf < 8; nf++) {
                    int kc = key0 + nf*8 + 2*tig;
                    if (kc     > rloc0) s[nf][0] = -1e30f;
                    if (kc + 1 > rloc0) s[nf][1] = -1e30f;
                    if (kc     > rloc1) s[nf][2] = -1e30f;
                    if (kc + 1 > rloc1) s[nf][3] = -1e30f;
                }
            }

            float mx0 = -1e30f, mx1 = -1e30f;
#pragma unroll
            for (int nf = 0; nf < 8; nf++) {
                mx0 = fmaxf(mx0, fmaxf(s[nf][0], s[nf][1]));
                mx1 = fmaxf(mx1, fmaxf(s[nf][2], s[nf][3]));
            }
            mx0 = fmaxf(mx0, __shfl_xor_sync(0xffffffffu, mx0, 1));
            mx0 = fmaxf(mx0, __shfl_xor_sync(0xffffffffu, mx0, 2));
            mx1 = fmaxf(mx1, __shfl_xor_sync(0xffffffffu, mx1, 1));
            mx1 = fmaxf(mx1, __shfl_xor_sync(0xffffffffu, mx1, 2));
            float mn0 = fmaxf(m0, mx0), mn1 = fmaxf(m1, mx1);
            float a0 = __expf(m0 - mn0), a1 = __expf(m1 - mn1);
            m0 = mn0; m1 = mn1;
            float sum0 = 0.f, sum1 = 0.f;
#pragma unroll
            for (int nf = 0; nf < 8; nf++) {
                s[nf][0] = __expf(s[nf][0] - mn0);
                s[nf][1] = __expf(s[nf][1] - mn0);
                s[nf][2] = __expf(s[nf][2] - mn1);
                s[nf][3] = __expf(s[nf][3] - mn1);
                sum0 += s[nf][0] + s[nf][1];
                sum1 += s[nf][2] + s[nf][3];
            }
            sum0 += __shfl_xor_sync(0xffffffffu, sum0, 1);
            sum0 += __shfl_xor_sync(0xffffffffu, sum0, 2);
            sum1 += __shfl_xor_sync(0xffffffffu, sum1, 1);
            sum1 += __shfl_xor_sync(0xffffffffu, sum1, 2);
            l0 = l0*a0 + sum0;
            l1 = l1*a1 + sum1;
#pragma unroll
            for (int nf = 0; nf < 8; nf++) {
                o[nf][0] *= a0; o[nf][1] *= a0;
                o[nf][2] *= a1; o[nf][3] *= a1;
            }

            // O += (Ph + Pl) @ Vh
#pragma unroll
            for (int sk = 0; sk < 4; sk++) {
                uint32_t ph[4], pl[4];
                split2(make_float2(s[2*sk][0],   s[2*sk][1]),   ph[0], pl[0]);
                split2(make_float2(s[2*sk][2],   s[2*sk][3]),   ph[1], pl[1]);
                split2(make_float2(s[2*sk+1][0], s[2*sk+1][1]), ph[2], pl[2]);
                split2(make_float2(s[2*sk+1][2], s[2*sk+1][3]), ph[3], pl[3]);
                const uint32_t vOff = bufB + 16384u + vRowB + (uint32_t)(sk*2048);
#pragma unroll
                for (int nb = 0; nb < 4; nb++) {
                    uint32_t vh4[4];
                    uint32_t co = (((uint32_t)(nb*32) + vColS) ^ swf);
                    ldsm4t(vh4, vOff + co);
                    mma16816(o[2*nb],   ph, vh4);
                    mma16816(o[2*nb+1], ph, vh4 + 2);
                    mma16816(o[2*nb],   pl, vh4);
                    mma16816(o[2*nb+1], pl, vh4 + 2);
                }
            }
        }
    }

    {
        float i0 = 1.f / l0, i1 = 1.f / l1;
        __half* base0 = gHs + (size_t)(b*SS + rloc0) * 1024;
        __half* base1 = gHs + (size_t)(b*SS + rloc1) * 1024;
#pragma unroll
        for (int nf = 0; nf < 8; nf++) {
            int col = h*64 + nf*8 + 2*tig;
            uint32_t hi, lo;
            split2(make_float2(o[nf][0]*i0, o[nf][1]*i0), hi, lo);
            *(uint32_t*)&base0[col]       = hi;
            *(uint32_t*)&base0[512 + col] = lo;
            split2(make_float2(o[nf][2]*i1, o[nf][3]*i1), hi, lo);
            *(uint32_t*)&base1[col]       = hi;
            *(uint32_t*)&base1[512 + col] = lo;
        }
    }
#undef LOAD_TILE
}

// ---------------------------------------------------------------------------
extern "C" void kernel_launch(void* const* d_in, const int* in_sizes, int n_in,
                              void* d_out, int out_size)
{
    const float* xs  = (const float*)d_in[0];
    const float* xt  = (const float*)d_in[1];
    const float* Wqs = (const float*)d_in[2];
    const float* Wks = (const float*)d_in[3];
    const float* Wvs = (const float*)d_in[4];
    const float* Wqt = (const float*)d_in[5];
    const float* Wkt = (const float*)d_in[6];
    const float* Wvt = (const float*)d_in[7];
    const float* WKb = (const float*)d_in[8];
    const float* Wo  = (const float*)d_in[9];
    float* out = (float*)d_out;

    const int GEMM_SMEM = 2 * 49152;      // 98304
    const int ATTN_SMEM = 2 * 24576;      // 49152
    cudaFuncSetAttribute(mma_gemm, cudaFuncAttributeMaxDynamicSharedMemorySize, GEMM_SMEM);
    cudaFuncSetAttribute(attn_mma, cudaFuncAttributeMaxDynamicSharedMemorySize, ATTN_SMEM);

    prep_all<<<4544, 256>>>(xs, xt, Wqs, Wks, Wvs, Wqt, Wkt, Wvt, Wo);

    mma_gemm<<<dim3(4, 64, 3), 256, GEMM_SMEM>>>(0, nullptr, WKb);
    attn_mma<<<512, 256, ATTN_SMEM>>>();
    mma_gemm<<<dim3(4, 64, 1), 256, GEMM_SMEM>>>(1, out, WKb);
}